// round 2
// baseline (speedup 1.0000x reference)
#include <cuda_runtime.h>
#include <math.h>

// ---------------------------------------------------------------------------
// RelationNetworks forward, fp32 baseline. B=1024, C=64, L=64, H=64, IMG=27.
// conv chain: 27 ->(s1) 25 ->(s1) 23 ->(s2) 11 ->(s2) 5
// ---------------------------------------------------------------------------

__device__ float d_buf1[1024 * 64 * 625];
__device__ float d_buf2[1024 * 64 * 529];
__device__ float d_buf3[1024 * 64 * 121];
__device__ float d_buf4[1024 * 64 * 25];
__device__ float d_Wt1[32 * 64];      // conv weights transposed to [k][oc]
__device__ float d_Wt2[576 * 64];
__device__ float d_Wt3[576 * 64];
__device__ float d_Wt4[576 * 64];
__device__ float d_stats[128];        // BN sum[64], sumsq[64]
__device__ float d_Ssum[2];           // attention softmax denominators
__device__ float d_bnss[128];         // current-layer BN scale[64], shift[64]
__device__ float d_g0[1024 * 64];
__device__ float d_g1[1024 * 64];

__global__ void zero_misc_kernel() {
    int t = threadIdx.x;
    if (t < 128) d_stats[t] = 0.f;
    if (t < 2) d_Ssum[t] = 0.f;
}

__global__ void prep_weights_kernel(const float* __restrict__ Wc1,
                                    const float* __restrict__ Wc2,
                                    const float* __restrict__ Wc3,
                                    const float* __restrict__ Wc4) {
    int i = blockIdx.x * blockDim.x + threadIdx.x;
    if (i < 64 * 27) {
        int oc = i / 27, k = i - oc * 27;
        d_Wt1[k * 64 + oc] = Wc1[i];
    }
    if (i < 64 * 576) {
        int oc = i / 576, k = i - oc * 576;
        d_Wt2[k * 64 + oc] = Wc2[i];
        d_Wt3[k * 64 + oc] = Wc3[i];
        d_Wt4[k * 64 + oc] = Wc4[i];
    }
}

// global sum of exp over all (b,c) for a0 = latents[:,2,:] and a1 = latents[:,3,:]
__global__ void att_sum_kernel(const float* __restrict__ lat) {
    int i = blockIdx.x * blockDim.x + threadIdx.x;
    float p0 = 0.f, p1 = 0.f;
    for (int idx = i; idx < 65536; idx += gridDim.x * blockDim.x) {
        int b = idx >> 6, c = idx & 63;
        p0 += expf(lat[(b * 4 + 2) * 64 + c]);
        p1 += expf(lat[(b * 4 + 3) * 64 + c]);
    }
#pragma unroll
    for (int o = 16; o; o >>= 1) {
        p0 += __shfl_down_sync(0xffffffffu, p0, o);
        p1 += __shfl_down_sync(0xffffffffu, p1, o);
    }
    if ((threadIdx.x & 31) == 0) {
        atomicAdd(&d_Ssum[0], p0);
        atomicAdd(&d_Ssum[1], p1);
    }
}

__global__ void bn_finalize_kernel(const float* __restrict__ bn_g,
                                   const float* __restrict__ bn_b,
                                   int layer, float invN) {
    int c = threadIdx.x;  // 64 threads
    float s = d_stats[c], q = d_stats[64 + c];
    float mean = s * invN;
    float var = q * invN - mean * mean;
    float sc = bn_g[layer * 64 + c] * rsqrtf(var + 1e-5f);
    d_bnss[c] = sc;
    d_bnss[64 + c] = bn_b[layer * 64 + c] - mean * sc;
    d_stats[c] = 0.f;
    d_stats[64 + c] = 0.f;
}

// implicit-GEMM conv. M = 1024*OH*OW (div by 64), N = 64 oc, K = CIN*9.
// FUSE: apply previous layer's BN scale/shift + relu to gathered inputs.
// Accumulates raw-output per-channel sum/sumsq into d_stats.
template <int CIN, int IH, int IW, int OH, int OW, int STRIDE, bool FUSE>
__global__ void __launch_bounds__(256) conv_gemm_kernel(
    const float* __restrict__ in, const float* __restrict__ Wt,
    float* __restrict__ out) {
    constexpr int K = CIN * 9;
    constexpr int OSP = OH * OW;
    constexpr int BK = 16;

    __shared__ float As[BK][64];
    __shared__ float Bs[BK][64];
    __shared__ float red[2][64][16];
    __shared__ float sOut[64 * 65];

    const int tid = threadIdx.x;
    const int tx = tid & 15, ty = tid >> 4;
    const int m0 = blockIdx.x * 64;

    const int mi = tid >> 2;          // row of A this thread gathers
    const int kb = (tid & 3) * 4;     // 4 consecutive k's
    const int mg = m0 + mi;
    const int bI = mg / OSP;
    const int spg = mg - bI * OSP;
    const int oyg = spg / OW;
    const int oxg = spg - oyg * OW;
    const float* inb = in + ((size_t)bI * CIN) * IH * IW + (oyg * STRIDE) * IW + oxg * STRIDE;

    float acc[4][4];
#pragma unroll
    for (int i = 0; i < 4; i++)
#pragma unroll
        for (int j = 0; j < 4; j++) acc[i][j] = 0.f;

    for (int k0 = 0; k0 < K; k0 += BK) {
        {
            int ki = tid >> 4;
            int oc = (tid & 15) * 4;
            float4 v = make_float4(0.f, 0.f, 0.f, 0.f);
            if (k0 + ki < K) v = *(const float4*)(Wt + (size_t)(k0 + ki) * 64 + oc);
            *(float4*)&Bs[ki][oc] = v;
        }
#pragma unroll
        for (int j = 0; j < 4; j++) {
            int k = k0 + kb + j;
            float v = 0.f;
            if (k < K) {
                int ic = k / 9;
                int r = k - ic * 9;
                int ky = r / 3;
                int kx = r - ky * 3;
                float x = inb[ic * IH * IW + ky * IW + kx];
                if (FUSE) x = fmaxf(fmaf(x, d_bnss[ic], d_bnss[64 + ic]), 0.f);
                v = x;
            }
            As[kb + j][mi] = v;
        }
        __syncthreads();
#pragma unroll
        for (int kk = 0; kk < BK; kk++) {
            float4 a4 = *(float4*)&As[kk][ty * 4];
            float4 b4 = *(float4*)&Bs[kk][tx * 4];
            float av[4] = {a4.x, a4.y, a4.z, a4.w};
            float bw[4] = {b4.x, b4.y, b4.z, b4.w};
#pragma unroll
            for (int i = 0; i < 4; i++)
#pragma unroll
                for (int j = 0; j < 4; j++)
                    acc[i][j] = fmaf(av[i], bw[j], acc[i][j]);
        }
        __syncthreads();
    }

#pragma unroll
    for (int j = 0; j < 4; j++) {
        float s = 0.f, q = 0.f;
#pragma unroll
        for (int i = 0; i < 4; i++) {
            float v = acc[i][j];
            s += v;
            q += v * v;
            sOut[(tx * 4 + j) * 65 + ty * 4 + i] = v;
        }
        red[0][tx * 4 + j][ty] = s;
        red[1][tx * 4 + j][ty] = q;
    }
    __syncthreads();

    for (int idx = tid; idx < 4096; idx += 256) {
        int oc = idx >> 6, ml = idx & 63;
        int mm = m0 + ml;
        int bb = mm / OSP;
        int spp = mm - bb * OSP;
        out[((size_t)bb * 64 + oc) * OSP + spp] = sOut[oc * 65 + ml];
    }
    if (tid < 128) {
        int s = tid >> 6, c = tid & 63;
        float v = 0.f;
#pragma unroll
        for (int t = 0; t < 16; t++) v += red[s][c][t];
        atomicAdd(&d_stats[tid], v);
    }
}

// one block per batch element: BN3+relu + attention scale on conv4 output,
// build ct/ti/tj/tw, run the 625-pair MLP, sum into gout[b][0:64].
__global__ void __launch_bounds__(256) relation_kernel(
    const float* __restrict__ conv4, const float* __restrict__ lat,
    const float* __restrict__ Wg1, const float* __restrict__ bg1,
    const float* __restrict__ Wg2, const float* __restrict__ bg2,
    const float* __restrict__ Wg3, const float* __restrict__ bg3,
    int im, float* __restrict__ gout) {
    extern __shared__ float sm[];
    float* sW2 = sm;             // 4096
    float* sW3 = sm + 4096;      // 4096
    float* sTi = sm + 8192;      // 1600
    float* sTj = sm + 9792;      // 1600
    float* sCT = sm + 11392;     // 25*66 = 1650
    float* sTw = sm + 13042;     // 64
    float* sH  = sm + 13106;     // 8 warps * 128
    float* sGp = sm + 14130;     // 8 * 64

    const int tid = threadIdx.x;
    const int b = blockIdx.x;
    const int lane = tid & 31, warp = tid >> 5;

    for (int i = tid; i < 4096; i += 256) {
        sW2[i] = Wg2[i];
        sW3[i] = Wg3[i];
    }

    const float invS = 1.f / (d_Ssum[im] + 1e-9f);
    const float* aRow = lat + ((size_t)b * 4 + 2 + im) * 64;
    const float* wRow = lat + ((size_t)b * 4 + im) * 64;

    for (int i = tid; i < 1600; i += 256) {
        int c = i / 25, p = i - c * 25;
        float v = conv4[((size_t)b * 64 + c) * 25 + p];
        v = fmaxf(fmaf(v, d_bnss[c], d_bnss[64 + c]), 0.f);
        v *= expf(aRow[c]) * invS;
        sCT[p * 66 + c] = v;
    }
    if (tid < 50) {
        int p = tid % 25, cc = tid / 25;
        sCT[p * 66 + 64 + cc] = (cc == 0) ? (float)(p % 5) - 2.f : (float)(p / 5) - 2.f;
    }
    if (tid < 64) {
        float acc = bg1[tid];
        for (int c = 0; c < 64; c++)
            acc = fmaf(wRow[c], Wg1[(132 + c) * 64 + tid], acc);
        sTw[tid] = acc;
    }
    __syncthreads();

    for (int o = tid; o < 1600; o += 256) {
        int p = o >> 6, h = o & 63;
        float aj = 0.f, ai = 0.f;
        for (int c = 0; c < 66; c++) {
            float ctv = sCT[p * 66 + c];
            aj = fmaf(ctv, Wg1[c * 64 + h], aj);
            ai = fmaf(ctv, Wg1[(66 + c) * 64 + h], ai);
        }
        sTj[p * 64 + h] = aj;
        sTi[p * 64 + h] = ai;
    }
    __syncthreads();

    const float twA = sTw[lane], twB = sTw[lane + 32];
    const float b2A = bg2[lane], b2B = bg2[lane + 32];
    const float b3A = bg3[lane], b3B = bg3[lane + 32];
    float gA = 0.f, gB = 0.f;
    float* hw = sH + warp * 128;

    for (int it = 0; it < 40; it++) {
        int pr0 = it * 16 + warp * 2;
        int pr1 = pr0 + 1;
        bool v0 = pr0 < 625, v1 = pr1 < 625;
        int p0 = v0 ? pr0 / 25 : 0, q0 = v0 ? pr0 % 25 : 0;
        int p1 = v1 ? pr1 / 25 : 0, q1 = v1 ? pr1 % 25 : 0;

        float hA0 = fmaxf(sTi[p0 * 64 + lane] + sTj[q0 * 64 + lane] + twA, 0.f);
        float hA1 = fmaxf(sTi[p0 * 64 + lane + 32] + sTj[q0 * 64 + lane + 32] + twB, 0.f);
        float hB0 = fmaxf(sTi[p1 * 64 + lane] + sTj[q1 * 64 + lane] + twA, 0.f);
        float hB1 = fmaxf(sTi[p1 * 64 + lane + 32] + sTj[q1 * 64 + lane + 32] + twB, 0.f);
        __syncwarp();
        hw[lane] = hA0;
        hw[lane + 32] = hA1;
        hw[64 + lane] = hB0;
        hw[64 + lane + 32] = hB1;
        __syncwarp();

        float aA0 = b2A, aA1 = b2B, aB0 = b2A, aB1 = b2B;
#pragma unroll 8
        for (int k = 0; k < 64; k++) {
            float w0 = sW2[k * 64 + lane], w1 = sW2[k * 64 + lane + 32];
            float hA = hw[k], hB = hw[64 + k];
            aA0 = fmaf(hA, w0, aA0);
            aA1 = fmaf(hA, w1, aA1);
            aB0 = fmaf(hB, w0, aB0);
            aB1 = fmaf(hB, w1, aB1);
        }
        __syncwarp();
        hw[lane] = fmaxf(aA0, 0.f);
        hw[lane + 32] = fmaxf(aA1, 0.f);
        hw[64 + lane] = fmaxf(aB0, 0.f);
        hw[64 + lane + 32] = fmaxf(aB1, 0.f);
        __syncwarp();

        aA0 = b3A; aA1 = b3B; aB0 = b3A; aB1 = b3B;
#pragma unroll 8
        for (int k = 0; k < 64; k++) {
            float w0 = sW3[k * 64 + lane], w1 = sW3[k * 64 + lane + 32];
            float hA = hw[k], hB = hw[64 + k];
            aA0 = fmaf(hA, w0, aA0);
            aA1 = fmaf(hA, w1, aA1);
            aB0 = fmaf(hB, w0, aB0);
            aB1 = fmaf(hB, w1, aB1);
        }
        if (v0) { gA += fmaxf(aA0, 0.f); gB += fmaxf(aA1, 0.f); }
        if (v1) { gA += fmaxf(aB0, 0.f); gB += fmaxf(aB1, 0.f); }
        __syncwarp();
    }
    sGp[warp * 64 + lane] = gA;
    sGp[warp * 64 + lane + 32] = gB;
    __syncthreads();
    if (tid < 64) {
        float s = 0.f;
#pragma unroll
        for (int w = 0; w < 8; w++) s += sGp[w * 64 + tid];
        gout[(size_t)b * 64 + tid] = s;
    }
}

__global__ void final_head_kernel(const float* __restrict__ lat,
                                  const float* __restrict__ Wf1, const float* __restrict__ bf1,
                                  const float* __restrict__ Wf2, const float* __restrict__ bf2,
                                  const float* __restrict__ Wf3, const float* __restrict__ bf3,
                                  float* __restrict__ out) {
    __shared__ float sh1[8][64];
    int tid = threadIdx.x, lane = tid & 31, warp = tid >> 5;
    int b = blockIdx.x * 8 + warp;
    float a0 = bf1[lane], a1 = bf1[lane + 32];
    const float* g0 = d_g0 + (size_t)b * 64;
    const float* g1 = d_g1 + (size_t)b * 64;
    const float* lr = lat + (size_t)b * 256;
    for (int k = 0; k < 64; k++) {
        float g = g0[k];
        a0 = fmaf(g, Wf1[k * 64 + lane], a0);
        a1 = fmaf(g, Wf1[k * 64 + lane + 32], a1);
    }
    for (int k = 0; k < 64; k++) {
        float g = g1[k];
        a0 = fmaf(g, Wf1[(64 + k) * 64 + lane], a0);
        a1 = fmaf(g, Wf1[(64 + k) * 64 + lane + 32], a1);
    }
    for (int k = 0; k < 256; k++) {
        float g = lr[k];
        a0 = fmaf(g, Wf1[(128 + k) * 64 + lane], a0);
        a1 = fmaf(g, Wf1[(128 + k) * 64 + lane + 32], a1);
    }
    sh1[warp][lane] = fmaxf(a0, 0.f);
    sh1[warp][lane + 32] = fmaxf(a1, 0.f);
    __syncwarp();
    float c = bf2[lane];
    for (int k = 0; k < 64; k++) c = fmaf(sh1[warp][k], Wf2[k * 32 + lane], c);
    c = fmaxf(c, 0.f);
    float v = c * Wf3[lane];
#pragma unroll
    for (int o = 16; o; o >>= 1) v += __shfl_down_sync(0xffffffffu, v, o);
    if (lane == 0) out[b] = v + bf3[0];
}

extern "C" void kernel_launch(void* const* d_in, const int* in_sizes, int n_in,
                              void* d_out, int out_size) {
    const float* x0 = (const float*)d_in[0];
    const float* x1 = (const float*)d_in[1];
    const float* lat = (const float*)d_in[2];
    const float* Wc1 = (const float*)d_in[3];
    const float* Wc2 = (const float*)d_in[4];
    const float* Wc3 = (const float*)d_in[5];
    const float* Wc4 = (const float*)d_in[6];
    const float* bng = (const float*)d_in[7];
    const float* bnb = (const float*)d_in[8];
    const float* Wg1 = (const float*)d_in[9];
    const float* bg1 = (const float*)d_in[10];
    const float* Wg2 = (const float*)d_in[11];
    const float* bg2 = (const float*)d_in[12];
    const float* Wg3 = (const float*)d_in[13];
    const float* bg3 = (const float*)d_in[14];
    const float* Wf1 = (const float*)d_in[15];
    const float* bf1 = (const float*)d_in[16];
    const float* Wf2 = (const float*)d_in[17];
    const float* bf2 = (const float*)d_in[18];
    const float* Wf3 = (const float*)d_in[19];
    const float* bf3 = (const float*)d_in[20];
    float* out = (float*)d_out;

    float *buf1, *buf2, *buf3, *buf4, *wt1, *wt2, *wt3, *wt4, *g0p, *g1p;
    cudaGetSymbolAddress((void**)&buf1, d_buf1);
    cudaGetSymbolAddress((void**)&buf2, d_buf2);
    cudaGetSymbolAddress((void**)&buf3, d_buf3);
    cudaGetSymbolAddress((void**)&buf4, d_buf4);
    cudaGetSymbolAddress((void**)&wt1, d_Wt1);
    cudaGetSymbolAddress((void**)&wt2, d_Wt2);
    cudaGetSymbolAddress((void**)&wt3, d_Wt3);
    cudaGetSymbolAddress((void**)&wt4, d_Wt4);
    cudaGetSymbolAddress((void**)&g0p, d_g0);
    cudaGetSymbolAddress((void**)&g1p, d_g1);

    const int REL_SMEM = 14642 * 4;
    cudaFuncSetAttribute(relation_kernel, cudaFuncAttributeMaxDynamicSharedMemorySize, REL_SMEM);

    zero_misc_kernel<<<1, 128>>>();
    prep_weights_kernel<<<144, 256>>>(Wc1, Wc2, Wc3, Wc4);
    att_sum_kernel<<<64, 512>>>(lat);

    for (int im = 0; im < 2; im++) {
        const float* x = im ? x1 : x0;
        float* gp = im ? g1p : g0p;
        conv_gemm_kernel<3, 27, 27, 25, 25, 1, false><<<10000, 256>>>(x, wt1, buf1);
        bn_finalize_kernel<<<1, 64>>>(bng, bnb, 0, 1.f / 640000.f);
        conv_gemm_kernel<64, 25, 25, 23, 23, 1, true><<<8464, 256>>>(buf1, wt2, buf2);
        bn_finalize_kernel<<<1, 64>>>(bng, bnb, 1, 1.f / 541696.f);
        conv_gemm_kernel<64, 23, 23, 11, 11, 2, true><<<1936, 256>>>(buf2, wt3, buf3);
        bn_finalize_kernel<<<1, 64>>>(bng, bnb, 2, 1.f / 123904.f);
        conv_gemm_kernel<64, 11, 11, 5, 5, 2, true><<<400, 256>>>(buf3, wt4, buf4);
        bn_finalize_kernel<<<1, 64>>>(bng, bnb, 3, 1.f / 25600.f);
        relation_kernel<<<1024, 256, REL_SMEM>>>(buf4, lat, Wg1, bg1, Wg2, bg2,
                                                 Wg3, bg3, im, gp);
    }
    final_head_kernel<<<128, 256>>>(lat, Wf1, bf1, Wf2, bf2, Wf3, bf3, out);
}

// round 4
// speedup vs baseline: 1.2186x; 1.2186x over previous
#include <cuda_runtime.h>
#include <math.h>

// ---------------------------------------------------------------------------
// RelationNetworks forward. B=1024, C=64, L=64, H=64, IMG=27.
// conv chain: 27 ->(s1) 25 ->(s1) 23 ->(s2) 11 ->(s2) 5
// All inter-layer activations stored NHWC: [b][sp][c], c=64 contiguous.
// ---------------------------------------------------------------------------

__device__ float d_buf1[1024 * 625 * 64];
__device__ float d_buf2[1024 * 529 * 64];
__device__ float d_buf3[1024 * 121 * 64];
__device__ float d_buf4[1024 * 25 * 64];
__device__ float d_Wt1[32 * 64];      // conv1 weights [k=(ky,kx,ic) padded to 32][oc]
__device__ float d_Wt2[576 * 64];     // [k=(ky*3+kx)*64+ic][oc]
__device__ float d_Wt3[576 * 64];
__device__ float d_Wt4[576 * 64];
__device__ float d_stats[128];        // BN sum[64], sumsq[64]
__device__ float d_Ssum[2];           // attention softmax denominators
__device__ float d_bnss[128];         // current-layer BN scale[64], shift[64]
__device__ float d_g0[1024 * 64];
__device__ float d_g1[1024 * 64];

__global__ void zero_misc_kernel() {
    int t = threadIdx.x;
    if (t < 128) d_stats[t] = 0.f;
    if (t < 2) d_Ssum[t] = 0.f;
}

// destination-major weight transpose:
//   Wt1[k*64+oc] = (k<27) ? Wc1[oc][ic=k%3][w=k/3] : 0     (w = ky*3+kx)
//   Wt234[k*64+oc] = Wc[oc][ic=k%64][w=k/64]
__global__ void prep_weights_kernel(const float* __restrict__ Wc1,
                                    const float* __restrict__ Wc2,
                                    const float* __restrict__ Wc3,
                                    const float* __restrict__ Wc4) {
    int i = blockIdx.x * blockDim.x + threadIdx.x;
    if (i < 32 * 64) {
        int k = i >> 6, oc = i & 63;
        d_Wt1[i] = (k < 27) ? Wc1[oc * 27 + (k % 3) * 9 + (k / 3)] : 0.f;
    }
    if (i < 576 * 64) {
        int k = i >> 6, oc = i & 63;
        int src = oc * 576 + (k & 63) * 9 + (k >> 6);
        d_Wt2[i] = Wc2[src];
        d_Wt3[i] = Wc3[src];
        d_Wt4[i] = Wc4[src];
    }
}

// global sum of exp over all (b,c) for a0 = latents[:,2,:] and a1 = latents[:,3,:]
__global__ void att_sum_kernel(const float* __restrict__ lat) {
    int i = blockIdx.x * blockDim.x + threadIdx.x;
    float p0 = 0.f, p1 = 0.f;
    for (int idx = i; idx < 65536; idx += gridDim.x * blockDim.x) {
        int b = idx >> 6, c = idx & 63;
        p0 += expf(lat[(b * 4 + 2) * 64 + c]);
        p1 += expf(lat[(b * 4 + 3) * 64 + c]);
    }
#pragma unroll
    for (int o = 16; o; o >>= 1) {
        p0 += __shfl_down_sync(0xffffffffu, p0, o);
        p1 += __shfl_down_sync(0xffffffffu, p1, o);
    }
    if ((threadIdx.x & 31) == 0) {
        atomicAdd(&d_Ssum[0], p0);
        atomicAdd(&d_Ssum[1], p1);
    }
}

__global__ void bn_finalize_kernel(const float* __restrict__ bn_g,
                                   const float* __restrict__ bn_b,
                                   int layer, float invN) {
    int c = threadIdx.x;  // 64 threads
    float s = d_stats[c], q = d_stats[64 + c];
    float mean = s * invN;
    float var = q * invN - mean * mean;
    float sc = bn_g[layer * 64 + c] * rsqrtf(var + 1e-5f);
    d_bnss[c] = sc;
    d_bnss[64 + c] = bn_b[layer * 64 + c] - mean * sc;
    d_stats[c] = 0.f;
    d_stats[64 + c] = 0.f;
}

// ---- shared epilogue: per-channel stats + direct NHWC store ---------------
__device__ __forceinline__ void conv_epilogue(
    float acc[4][4], float* __restrict__ out, int m0, int tid, int tx, int ty,
    float (*red)[64][16]) {
#pragma unroll
    for (int j = 0; j < 4; j++) {
        float s = 0.f, q = 0.f;
#pragma unroll
        for (int i = 0; i < 4; i++) {
            float v = acc[i][j];
            s += v;
            q += v * v;
        }
        red[0][tx * 4 + j][ty] = s;
        red[1][tx * 4 + j][ty] = q;
    }
#pragma unroll
    for (int i = 0; i < 4; i++) {
        float4 v = make_float4(acc[i][0], acc[i][1], acc[i][2], acc[i][3]);
        *(float4*)(out + (size_t)(m0 + ty * 4 + i) * 64 + tx * 4) = v;
    }
    __syncthreads();
    if (tid < 128) {
        int s = tid >> 6, c = tid & 63;
        float v = 0.f;
#pragma unroll
        for (int t = 0; t < 16; t++) v += red[s][c][t];
        atomicAdd(&d_stats[tid], v);
    }
}

// ---- conv1: NCHW input (3 channels), NHWC output --------------------------
__global__ void __launch_bounds__(256) conv1_kernel(
    const float* __restrict__ in, const float* __restrict__ Wt,
    float* __restrict__ out) {
    constexpr int BK = 16;
    __shared__ float As[BK][64];
    __shared__ float Bs[BK][64];
    __shared__ float red[2][64][16];

    const int tid = threadIdx.x;
    const int tx = tid & 15, ty = tid >> 4;
    const int m0 = blockIdx.x * 64;

    const int mi = tid >> 2;
    const int kb = (tid & 3) * 4;
    const int mg = m0 + mi;
    const int bI = mg / 625;
    const int sp = mg - bI * 625;
    const int oy = sp / 25;
    const int ox = sp - oy * 25;
    const float* inb = in + ((size_t)bI * 3) * 729 + oy * 27 + ox;

    float acc[4][4];
#pragma unroll
    for (int i = 0; i < 4; i++)
#pragma unroll
        for (int j = 0; j < 4; j++) acc[i][j] = 0.f;

    for (int k0 = 0; k0 < 32; k0 += BK) {
        {
            int ki = tid >> 4;
            int oc = (tid & 15) * 4;
            *(float4*)&Bs[ki][oc] = *(const float4*)(Wt + (k0 + ki) * 64 + oc);
        }
#pragma unroll
        for (int j = 0; j < 4; j++) {
            int k = k0 + kb + j;
            float v = 0.f;
            if (k < 27) {
                int w = k / 3, ic = k - w * 3;
                int ky = w / 3, kx = w - ky * 3;
                v = inb[ic * 729 + ky * 27 + kx];
            }
            As[kb + j][mi] = v;
        }
        __syncthreads();
#pragma unroll
        for (int kk = 0; kk < BK; kk++) {
            float4 a4 = *(float4*)&As[kk][ty * 4];
            float4 b4 = *(float4*)&Bs[kk][tx * 4];
            float av[4] = {a4.x, a4.y, a4.z, a4.w};
            float bw[4] = {b4.x, b4.y, b4.z, b4.w};
#pragma unroll
            for (int i = 0; i < 4; i++)
#pragma unroll
                for (int j = 0; j < 4; j++)
                    acc[i][j] = fmaf(av[i], bw[j], acc[i][j]);
        }
        __syncthreads();
    }
    conv_epilogue(acc, out, m0, tid, tx, ty, red);
}

// ---- conv with CIN=64, NHWC in/out, fused prev-layer BN+ReLU on gather ----
template <int IH, int IW, int OH, int OW, int STRIDE>
__global__ void __launch_bounds__(256) conv64_kernel(
    const float* __restrict__ in, const float* __restrict__ Wt,
    float* __restrict__ out) {
    constexpr int OSP = OH * OW;
    constexpr int BK = 16;
    __shared__ float As[BK][64];
    __shared__ float Bs[BK][64];
    __shared__ float red[2][64][16];

    const int tid = threadIdx.x;
    const int tx = tid & 15, ty = tid >> 4;
    const int m0 = blockIdx.x * 64;

    const int mi = tid >> 2;          // A row this thread gathers
    const int icq = (tid & 3) * 4;    // ic quad within BK block
    const int mg = m0 + mi;
    const int bI = mg / OSP;
    const int sp = mg - bI * OSP;
    const int oy = sp / OW;
    const int ox = sp - oy * OW;
    const float* inb = in + (((size_t)bI * IH + oy * STRIDE) * IW + ox * STRIDE) * 64;

    float acc[4][4];
#pragma unroll
    for (int i = 0; i < 4; i++)
#pragma unroll
        for (int j = 0; j < 4; j++) acc[i][j] = 0.f;

#pragma unroll 1
    for (int k0 = 0; k0 < 576; k0 += BK) {
        const int w = k0 >> 6;            // window index ky*3+kx
        const int ic0 = k0 & 63;
        const int ky = w / 3, kx = w - ky * 3;
        {
            int ki = tid >> 4;
            int oc = (tid & 15) * 4;
            *(float4*)&Bs[ki][oc] = *(const float4*)(Wt + (size_t)(k0 + ki) * 64 + oc);
        }
        {
            int ic = ic0 + icq;
            float4 v = *(const float4*)(inb + (ky * IW + kx) * 64 + ic);
            float4 sc = *(const float4*)&d_bnss[ic];
            float4 sh = *(const float4*)&d_bnss[64 + ic];
            As[icq + 0][mi] = fmaxf(fmaf(v.x, sc.x, sh.x), 0.f);
            As[icq + 1][mi] = fmaxf(fmaf(v.y, sc.y, sh.y), 0.f);
            As[icq + 2][mi] = fmaxf(fmaf(v.z, sc.z, sh.z), 0.f);
            As[icq + 3][mi] = fmaxf(fmaf(v.w, sc.w, sh.w), 0.f);
        }
        __syncthreads();
#pragma unroll
        for (int kk = 0; kk < BK; kk++) {
            float4 a4 = *(float4*)&As[kk][ty * 4];
            float4 b4 = *(float4*)&Bs[kk][tx * 4];
            float av[4] = {a4.x, a4.y, a4.z, a4.w};
            float bw[4] = {b4.x, b4.y, b4.z, b4.w};
#pragma unroll
            for (int i = 0; i < 4; i++)
#pragma unroll
                for (int j = 0; j < 4; j++)
                    acc[i][j] = fmaf(av[i], bw[j], acc[i][j]);
        }
        __syncthreads();
    }
    conv_epilogue(acc, out, m0, tid, tx, ty, red);
}

// ---- relation network: one block per batch element ------------------------
// conv4 is NHWC [b][p][c]. 8 warps x 4 pairs per iteration.
__global__ void __launch_bounds__(256) relation_kernel(
    const float* __restrict__ conv4, const float* __restrict__ lat,
    const float* __restrict__ Wg1, const float* __restrict__ bg1,
    const float* __restrict__ Wg2, const float* __restrict__ bg2,
    const float* __restrict__ Wg3, const float* __restrict__ bg3,
    int im, float* __restrict__ gout) {
    extern __shared__ float sm[];
    float* sW2 = sm;              // 4096
    float* sW3 = sm + 4096;       // 4096
    float* sTi = sm + 8192;       // 1600
    float* sTj = sm + 9792;       // 1600
    float* sCT = sm + 11392;      // 25*66 = 1650
    float* sTw = sm + 13042;      // 64
    float* sH  = sm + 13106;      // 8 warps * 256
    float* sGp = sm + 15154;      // 8 * 64  -> total 15666 floats

    const int tid = threadIdx.x;
    const int b = blockIdx.x;
    const int lane = tid & 31, warp = tid >> 5;

    for (int i = tid; i < 4096; i += 256) {
        sW2[i] = Wg2[i];
        sW3[i] = Wg3[i];
    }

    const float invS = 1.f / (d_Ssum[im] + 1e-9f);
    const float* aRow = lat + ((size_t)b * 4 + 2 + im) * 64;
    const float* wRow = lat + ((size_t)b * 4 + im) * 64;

    for (int i = tid; i < 1600; i += 256) {
        int p = i >> 6, c = i & 63;
        float v = conv4[((size_t)b * 25 + p) * 64 + c];
        v = fmaxf(fmaf(v, d_bnss[c], d_bnss[64 + c]), 0.f);
        v *= expf(aRow[c]) * invS;
        sCT[p * 66 + c] = v;
    }
    if (tid < 50) {
        int p = tid % 25, cc = tid / 25;
        sCT[p * 66 + 64 + cc] = (cc == 0) ? (float)(p % 5) - 2.f : (float)(p / 5) - 2.f;
    }
    if (tid < 64) {
        float acc = bg1[tid];
        for (int c = 0; c < 64; c++)
            acc = fmaf(wRow[c], Wg1[(132 + c) * 64 + tid], acc);
        sTw[tid] = acc;
    }
    __syncthreads();

    for (int o = tid; o < 1600; o += 256) {
        int p = o >> 6, h = o & 63;
        float aj = 0.f, ai = 0.f;
        for (int c = 0; c < 66; c++) {
            float ctv = sCT[p * 66 + c];
            aj = fmaf(ctv, Wg1[c * 64 + h], aj);
            ai = fmaf(ctv, Wg1[(66 + c) * 64 + h], ai);
        }
        sTj[p * 64 + h] = aj;
        sTi[p * 64 + h] = ai;
    }
    __syncthreads();

    const float twA = sTw[lane], twB = sTw[lane + 32];
    const float b2A = bg2[lane], b2B = bg2[lane + 32];
    const float b3A = bg3[lane], b3B = bg3[lane + 32];
    float gA = 0.f, gB = 0.f;
    float* hw = sH + warp * 256;

    for (int it = 0; it < 20; it++) {
        const int base = it * 32 + warp * 4;
#pragma unroll
        for (int s = 0; s < 4; s++) {
            int pr = base + s;
            bool vld = pr < 625;
            int p = vld ? pr / 25 : 0, qq = vld ? pr % 25 : 0;
            float h0 = fmaxf(sTi[p * 64 + lane] + sTj[qq * 64 + lane] + twA, 0.f);
            float h1 = fmaxf(sTi[p * 64 + lane + 32] + sTj[qq * 64 + lane + 32] + twB, 0.f);
            hw[s * 64 + lane] = h0;
            hw[s * 64 + lane + 32] = h1;
        }
        __syncwarp();

        float a0[4], a1[4];
#pragma unroll
        for (int s = 0; s < 4; s++) { a0[s] = b2A; a1[s] = b2B; }
#pragma unroll 8
        for (int k = 0; k < 64; k++) {
            float w0 = sW2[k * 64 + lane], w1 = sW2[k * 64 + lane + 32];
#pragma unroll
            for (int s = 0; s < 4; s++) {
                float h = hw[s * 64 + k];
                a0[s] = fmaf(h, w0, a0[s]);
                a1[s] = fmaf(h, w1, a1[s]);
            }
        }
        __syncwarp();
#pragma unroll
        for (int s = 0; s < 4; s++) {
            hw[s * 64 + lane] = fmaxf(a0[s], 0.f);
            hw[s * 64 + lane + 32] = fmaxf(a1[s], 0.f);
        }
        __syncwarp();

#pragma unroll
        for (int s = 0; s < 4; s++) { a0[s] = b3A; a1[s] = b3B; }
#pragma unroll 8
        for (int k = 0; k < 64; k++) {
            float w0 = sW3[k * 64 + lane], w1 = sW3[k * 64 + lane + 32];
#pragma unroll
            for (int s = 0; s < 4; s++) {
                float h = hw[s * 64 + k];
                a0[s] = fmaf(h, w0, a0[s]);
                a1[s] = fmaf(h, w1, a1[s]);
            }
        }
#pragma unroll
        for (int s = 0; s < 4; s++) {
            if (base + s < 625) {
                gA += fmaxf(a0[s], 0.f);
                gB += fmaxf(a1[s], 0.f);
            }
        }
        __syncwarp();
    }
    sGp[warp * 64 + lane] = gA;
    sGp[warp * 64 + lane + 32] = gB;
    __syncthreads();
    if (tid < 64) {
        float s = 0.f;
#pragma unroll
        for (int w = 0; w < 8; w++) s += sGp[w * 64 + tid];
        gout[(size_t)b * 64 + tid] = s;
    }
}

__global__ void final_head_kernel(const float* __restrict__ lat,
                                  const float* __restrict__ Wf1, const float* __restrict__ bf1,
                                  const float* __restrict__ Wf2, const float* __restrict__ bf2,
                                  const float* __restrict__ Wf3, const float* __restrict__ bf3,
                                  float* __restrict__ out) {
    __shared__ float sh1[8][64];
    int tid = threadIdx.x, lane = tid & 31, warp = tid >> 5;
    int b = blockIdx.x * 8 + warp;
    float a0 = bf1[lane], a1 = bf1[lane + 32];
    const float* g0 = d_g0 + (size_t)b * 64;
    const float* g1 = d_g1 + (size_t)b * 64;
    const float* lr = lat + (size_t)b * 256;
    for (int k = 0; k < 64; k++) {
        float g = g0[k];
        a0 = fmaf(g, Wf1[k * 64 + lane], a0);
        a1 = fmaf(g, Wf1[k * 64 + lane + 32], a1);
    }
    for (int k = 0; k < 64; k++) {
        float g = g1[k];
        a0 = fmaf(g, Wf1[(64 + k) * 64 + lane], a0);
        a1 = fmaf(g, Wf1[(64 + k) * 64 + lane + 32], a1);
    }
    for (int k = 0; k < 256; k++) {
        float g = lr[k];
        a0 = fmaf(g, Wf1[(128 + k) * 64 + lane], a0);
        a1 = fmaf(g, Wf1[(128 + k) * 64 + lane + 32], a1);
    }
    sh1[warp][lane] = fmaxf(a0, 0.f);
    sh1[warp][lane + 32] = fmaxf(a1, 0.f);
    __syncwarp();
    float c = bf2[lane];
    for (int k = 0; k < 64; k++) c = fmaf(sh1[warp][k], Wf2[k * 32 + lane], c);
    c = fmaxf(c, 0.f);
    float v = c * Wf3[lane];
#pragma unroll
    for (int o = 16; o; o >>= 1) v += __shfl_down_sync(0xffffffffu, v, o);
    if (lane == 0) out[b] = v + bf3[0];
}

extern "C" void kernel_launch(void* const* d_in, const int* in_sizes, int n_in,
                              void* d_out, int out_size) {
    const float* x0 = (const float*)d_in[0];
    const float* x1 = (const float*)d_in[1];
    const float* lat = (const float*)d_in[2];
    const float* Wc1 = (const float*)d_in[3];
    const float* Wc2 = (const float*)d_in[4];
    const float* Wc3 = (const float*)d_in[5];
    const float* Wc4 = (const float*)d_in[6];
    const float* bng = (const float*)d_in[7];
    const float* bnb = (const float*)d_in[8];
    const float* Wg1 = (const float*)d_in[9];
    const float* bg1 = (const float*)d_in[10];
    const float* Wg2 = (const float*)d_in[11];
    const float* bg2 = (const float*)d_in[12];
    const float* Wg3 = (const float*)d_in[13];
    const float* bg3 = (const float*)d_in[14];
    const float* Wf1 = (const float*)d_in[15];
    const float* bf1 = (const float*)d_in[16];
    const float* Wf2 = (const float*)d_in[17];
    const float* bf2 = (const float*)d_in[18];
    const float* Wf3 = (const float*)d_in[19];
    const float* bf3 = (const float*)d_in[20];
    float* out = (float*)d_out;

    float *buf1, *buf2, *buf3, *buf4, *wt1, *wt2, *wt3, *wt4, *g0p, *g1p;
    cudaGetSymbolAddress((void**)&buf1, d_buf1);
    cudaGetSymbolAddress((void**)&buf2, d_buf2);
    cudaGetSymbolAddress((void**)&buf3, d_buf3);
    cudaGetSymbolAddress((void**)&buf4, d_buf4);
    cudaGetSymbolAddress((void**)&wt1, d_Wt1);
    cudaGetSymbolAddress((void**)&wt2, d_Wt2);
    cudaGetSymbolAddress((void**)&wt3, d_Wt3);
    cudaGetSymbolAddress((void**)&wt4, d_Wt4);
    cudaGetSymbolAddress((void**)&g0p, d_g0);
    cudaGetSymbolAddress((void**)&g1p, d_g1);

    const int REL_SMEM = 15666 * 4;
    cudaFuncSetAttribute(relation_kernel, cudaFuncAttributeMaxDynamicSharedMemorySize, REL_SMEM);

    zero_misc_kernel<<<1, 128>>>();
    prep_weights_kernel<<<144, 256>>>(Wc1, Wc2, Wc3, Wc4);
    att_sum_kernel<<<64, 512>>>(lat);

    for (int im = 0; im < 2; im++) {
        const float* x = im ? x1 : x0;
        float* gp = im ? g1p : g0p;
        conv1_kernel<<<10000, 256>>>(x, wt1, buf1);
        bn_finalize_kernel<<<1, 64>>>(bng, bnb, 0, 1.f / 640000.f);
        conv64_kernel<25, 25, 23, 23, 1><<<8464, 256>>>(buf1, wt2, buf2);
        bn_finalize_kernel<<<1, 64>>>(bng, bnb, 1, 1.f / 541696.f);
        conv64_kernel<23, 23, 11, 11, 2><<<1936, 256>>>(buf2, wt3, buf3);
        bn_finalize_kernel<<<1, 64>>>(bng, bnb, 2, 1.f / 123904.f);
        conv64_kernel<11, 11, 5, 5, 2><<<400, 256>>>(buf3, wt4, buf4);
        bn_finalize_kernel<<<1, 64>>>(bng, bnb, 3, 1.f / 25600.f);
        relation_kernel<<<1024, 256, REL_SMEM>>>(buf4, lat, Wg1, bg1, Wg2, bg2,
                                                 Wg3, bg3, im, gp);
    }
    final_head_kernel<<<128, 256>>>(lat, Wf1, bf1, Wf2, bf2, Wf3, bf3, out);
}

// round 5
// speedup vs baseline: 1.2716x; 1.0435x over previous
#include <cuda_runtime.h>
#include <math.h>

// ---------------------------------------------------------------------------
// RelationNetworks forward. B=1024, C=64, L=64, H=64, IMG=27.
// conv chain: 27 ->(s1) 25 ->(s1) 23 ->(s2) 11 ->(s2) 5
// Activations NHWC: [b][sp][c], c=64 contiguous.
// ---------------------------------------------------------------------------

__device__ float d_buf1[1024 * 625 * 64];
__device__ float d_buf2[1024 * 529 * 64];
__device__ float d_buf3[1024 * 121 * 64];
__device__ float d_buf4[1024 * 25 * 64];
__device__ float d_Wt1[32 * 64];      // conv1 weights [k=(ky,kx,ic) pad 32][oc]
__device__ float d_Wt2[576 * 64];     // [k=(ky*3+kx)*64+ic][oc]
__device__ float d_Wt3[576 * 64];
__device__ float d_Wt4[576 * 64];
__device__ float d_stats[128];        // BN sum[64], sumsq[64]
__device__ float d_Ssum[2];           // attention softmax denominators
__device__ float d_bnss[128];         // current-layer BN scale[64], shift[64]
__device__ float d_g0[1024 * 64];
__device__ float d_g1[1024 * 64];

__global__ void zero_misc_kernel() {
    int t = threadIdx.x;
    if (t < 128) d_stats[t] = 0.f;
    if (t < 2) d_Ssum[t] = 0.f;
}

__global__ void prep_weights_kernel(const float* __restrict__ Wc1,
                                    const float* __restrict__ Wc2,
                                    const float* __restrict__ Wc3,
                                    const float* __restrict__ Wc4) {
    int i = blockIdx.x * blockDim.x + threadIdx.x;
    if (i < 32 * 64) {
        int k = i >> 6, oc = i & 63;
        d_Wt1[i] = (k < 27) ? Wc1[oc * 27 + (k % 3) * 9 + (k / 3)] : 0.f;
    }
    if (i < 576 * 64) {
        int k = i >> 6, oc = i & 63;
        int src = oc * 576 + (k & 63) * 9 + (k >> 6);
        d_Wt2[i] = Wc2[src];
        d_Wt3[i] = Wc3[src];
        d_Wt4[i] = Wc4[src];
    }
}

__global__ void att_sum_kernel(const float* __restrict__ lat) {
    int i = blockIdx.x * blockDim.x + threadIdx.x;
    float p0 = 0.f, p1 = 0.f;
    for (int idx = i; idx < 65536; idx += gridDim.x * blockDim.x) {
        int b = idx >> 6, c = idx & 63;
        p0 += expf(lat[(b * 4 + 2) * 64 + c]);
        p1 += expf(lat[(b * 4 + 3) * 64 + c]);
    }
#pragma unroll
    for (int o = 16; o; o >>= 1) {
        p0 += __shfl_down_sync(0xffffffffu, p0, o);
        p1 += __shfl_down_sync(0xffffffffu, p1, o);
    }
    if ((threadIdx.x & 31) == 0) {
        atomicAdd(&d_Ssum[0], p0);
        atomicAdd(&d_Ssum[1], p1);
    }
}

__global__ void bn_finalize_kernel(const float* __restrict__ bn_g,
                                   const float* __restrict__ bn_b,
                                   int layer, float invN) {
    int c = threadIdx.x;  // 64 threads
    float s = d_stats[c], q = d_stats[64 + c];
    float mean = s * invN;
    float var = q * invN - mean * mean;
    float sc = bn_g[layer * 64 + c] * rsqrtf(var + 1e-5f);
    d_bnss[c] = sc;
    d_bnss[64 + c] = bn_b[layer * 64 + c] - mean * sc;
    d_stats[c] = 0.f;
    d_stats[64 + c] = 0.f;
}

// ---- conv1: NCHW input (3 ch), NHWC output. 64x64 tile, 4x4/thread -------
__global__ void __launch_bounds__(256) conv1_kernel(
    const float* __restrict__ in, const float* __restrict__ Wt,
    float* __restrict__ out) {
    constexpr int BK = 16;
    __shared__ float As[BK][64];
    __shared__ float Bs[BK][64];
    __shared__ float red[2][64][16];

    const int tid = threadIdx.x;
    const int tx = tid & 15, ty = tid >> 4;
    const int m0 = blockIdx.x * 64;

    const int mi = tid >> 2;
    const int kb = (tid & 3) * 4;
    const int mg = m0 + mi;
    const int bI = mg / 625;
    const int sp = mg - bI * 625;
    const int oy = sp / 25;
    const int ox = sp - oy * 25;
    const float* inb = in + ((size_t)bI * 3) * 729 + oy * 27 + ox;

    float acc[4][4];
#pragma unroll
    for (int i = 0; i < 4; i++)
#pragma unroll
        for (int j = 0; j < 4; j++) acc[i][j] = 0.f;

    for (int k0 = 0; k0 < 32; k0 += BK) {
        {
            int ki = tid >> 4;
            int oc = (tid & 15) * 4;
            *(float4*)&Bs[ki][oc] = *(const float4*)(Wt + (k0 + ki) * 64 + oc);
        }
#pragma unroll
        for (int j = 0; j < 4; j++) {
            int k = k0 + kb + j;
            float v = 0.f;
            if (k < 27) {
                int w = k / 3, ic = k - w * 3;
                int ky = w / 3, kx = w - ky * 3;
                v = inb[ic * 729 + ky * 27 + kx];
            }
            As[kb + j][mi] = v;
        }
        __syncthreads();
#pragma unroll
        for (int kk = 0; kk < BK; kk++) {
            float4 a4 = *(float4*)&As[kk][ty * 4];
            float4 b4 = *(float4*)&Bs[kk][tx * 4];
            float av[4] = {a4.x, a4.y, a4.z, a4.w};
            float bw[4] = {b4.x, b4.y, b4.z, b4.w};
#pragma unroll
            for (int i = 0; i < 4; i++)
#pragma unroll
                for (int j = 0; j < 4; j++)
                    acc[i][j] = fmaf(av[i], bw[j], acc[i][j]);
        }
        __syncthreads();
    }
#pragma unroll
    for (int j = 0; j < 4; j++) {
        float s = 0.f, q = 0.f;
#pragma unroll
        for (int i = 0; i < 4; i++) {
            float v = acc[i][j];
            s += v;
            q += v * v;
        }
        red[0][tx * 4 + j][ty] = s;
        red[1][tx * 4 + j][ty] = q;
    }
#pragma unroll
    for (int i = 0; i < 4; i++) {
        float4 v = make_float4(acc[i][0], acc[i][1], acc[i][2], acc[i][3]);
        *(float4*)(out + (size_t)(m0 + ty * 4 + i) * 64 + tx * 4) = v;
    }
    __syncthreads();
    if (tid < 128) {
        int s = tid >> 6, c = tid & 63;
        float v = 0.f;
#pragma unroll
        for (int t = 0; t < 16; t++) v += red[s][c][t];
        atomicAdd(&d_stats[tid], v);
    }
}

// ---- conv64 v2: 128x64 tile, 128 threads, 8x8 regs/thread, NHWC ----------
template <int IH, int IW, int OH, int OW, int STRIDE>
__global__ void __launch_bounds__(128) conv64_kernel(
    const float* __restrict__ in, const float* __restrict__ Wt,
    float* __restrict__ out) {
    constexpr int OSP = OH * OW;
    constexpr int BK = 16;
    __shared__ float As[BK][128];
    __shared__ float Bs[BK][64];
    __shared__ float red[2][64][16];
    __shared__ float sBn[128];

    const int tid = threadIdx.x;
    const int tx = tid & 7;        // oc block: tx*8
    const int ty = tid >> 3;       // row block: ty*8 (0..15)
    const int m0 = blockIdx.x * 128;

    // gather: one A row per thread
    const int mg = m0 + tid;
    const int bI = mg / OSP;
    const int sp = mg - bI * OSP;
    const int oy = sp / OW;
    const int ox = sp - oy * OW;
    const float* inb = in + (((size_t)bI * IH + oy * STRIDE) * IW + ox * STRIDE) * 64;

    sBn[tid] = d_bnss[tid];

    float acc[8][8];
#pragma unroll
    for (int i = 0; i < 8; i++)
#pragma unroll
        for (int j = 0; j < 8; j++) acc[i][j] = 0.f;

    __syncthreads();

#pragma unroll 1
    for (int k0 = 0; k0 < 576; k0 += BK) {
        const int w = k0 >> 6;           // window ky*3+kx (BK=16 divides 64)
        const int ic0 = k0 & 63;
        const int ky = w / 3, kx = w - ky * 3;
        {   // B tile: 16x64 floats, 8 per thread
            int ki = tid >> 3;
            int oc = (tid & 7) * 8;
            const float* bw = Wt + (size_t)(k0 + ki) * 64 + oc;
            *(float4*)&Bs[ki][oc] = *(const float4*)bw;
            *(float4*)&Bs[ki][oc + 4] = *(const float4*)(bw + 4);
        }
        {   // A tile: this thread's row, 16 consecutive ic, fused BN+ReLU
            const float* src = inb + (ky * IW + kx) * 64 + ic0;
#pragma unroll
            for (int j = 0; j < 4; j++) {
                float4 v = *(const float4*)(src + j * 4);
                float4 sc = *(const float4*)&sBn[ic0 + j * 4];
                float4 sh = *(const float4*)&sBn[64 + ic0 + j * 4];
                As[j * 4 + 0][tid] = fmaxf(fmaf(v.x, sc.x, sh.x), 0.f);
                As[j * 4 + 1][tid] = fmaxf(fmaf(v.y, sc.y, sh.y), 0.f);
                As[j * 4 + 2][tid] = fmaxf(fmaf(v.z, sc.z, sh.z), 0.f);
                As[j * 4 + 3][tid] = fmaxf(fmaf(v.w, sc.w, sh.w), 0.f);
            }
        }
        __syncthreads();
#pragma unroll
        for (int kk = 0; kk < BK; kk++) {
            float4 a0 = *(float4*)&As[kk][ty * 8];
            float4 a1 = *(float4*)&As[kk][ty * 8 + 4];
            float4 b0 = *(float4*)&Bs[kk][tx * 8];
            float4 b1 = *(float4*)&Bs[kk][tx * 8 + 4];
            float av[8] = {a0.x, a0.y, a0.z, a0.w, a1.x, a1.y, a1.z, a1.w};
            float bw[8] = {b0.x, b0.y, b0.z, b0.w, b1.x, b1.y, b1.z, b1.w};
#pragma unroll
            for (int i = 0; i < 8; i++)
#pragma unroll
                for (int j = 0; j < 8; j++)
                    acc[i][j] = fmaf(av[i], bw[j], acc[i][j]);
        }
        __syncthreads();
    }

    // stats partials + NHWC stores
#pragma unroll
    for (int j = 0; j < 8; j++) {
        float s = 0.f, q = 0.f;
#pragma unroll
        for (int i = 0; i < 8; i++) {
            float v = acc[i][j];
            s += v;
            q += v * v;
        }
        red[0][tx * 8 + j][ty] = s;
        red[1][tx * 8 + j][ty] = q;
    }
#pragma unroll
    for (int i = 0; i < 8; i++) {
        float* dst = out + (size_t)(m0 + ty * 8 + i) * 64 + tx * 8;
        *(float4*)dst = make_float4(acc[i][0], acc[i][1], acc[i][2], acc[i][3]);
        *(float4*)(dst + 4) = make_float4(acc[i][4], acc[i][5], acc[i][6], acc[i][7]);
    }
    __syncthreads();
    {
        int s = tid >> 6, c = tid & 63;
        float v = 0.f;
#pragma unroll
        for (int t = 0; t < 16; t++) v += red[s][c][t];
        atomicAdd(&d_stats[tid], v);
    }
}

// ---- relation network: one block per batch element ------------------------
// conv4 NHWC [b][p][c]. 8 warps x 4 pairs; h stored [k*4+s] for float4 reads.
__global__ void __launch_bounds__(256) relation_kernel(
    const float* __restrict__ conv4, const float* __restrict__ lat,
    const float* __restrict__ Wg1, const float* __restrict__ bg1,
    const float* __restrict__ Wg2, const float* __restrict__ bg2,
    const float* __restrict__ Wg3, const float* __restrict__ bg3,
    int im, float* __restrict__ gout) {
    extern __shared__ float sm[];
    float* sW2 = sm;              // 4096
    float* sW3 = sm + 4096;       // 4096
    float* sTi = sm + 8192;       // 1600
    float* sTj = sm + 9792;       // 1600
    float* sCT = sm + 11392;      // 1650
    float* sTw = sm + 13042;      // 64
    float* sH  = sm + 13108;      // 8 warps * 256 (16B aligned)
    float* sGp = sm + 15156;      // 8 * 64  -> total 15668 floats

    const int tid = threadIdx.x;
    const int b = blockIdx.x;
    const int lane = tid & 31, warp = tid >> 5;

    for (int i = tid; i < 4096; i += 256) {
        sW2[i] = Wg2[i];
        sW3[i] = Wg3[i];
    }

    const float invS = 1.f / (d_Ssum[im] + 1e-9f);
    const float* aRow = lat + ((size_t)b * 4 + 2 + im) * 64;
    const float* wRow = lat + ((size_t)b * 4 + im) * 64;

    for (int i = tid; i < 1600; i += 256) {
        int p = i >> 6, c = i & 63;
        float v = conv4[((size_t)b * 25 + p) * 64 + c];
        v = fmaxf(fmaf(v, d_bnss[c], d_bnss[64 + c]), 0.f);
        v *= expf(aRow[c]) * invS;
        sCT[p * 66 + c] = v;
    }
    if (tid < 50) {
        int p = tid % 25, cc = tid / 25;
        sCT[p * 66 + 64 + cc] = (cc == 0) ? (float)(p % 5) - 2.f : (float)(p / 5) - 2.f;
    }
    if (tid < 64) {
        float acc = bg1[tid];
        for (int c = 0; c < 64; c++)
            acc = fmaf(wRow[c], Wg1[(132 + c) * 64 + tid], acc);
        sTw[tid] = acc;
    }
    __syncthreads();

    for (int o = tid; o < 1600; o += 256) {
        int p = o >> 6, h = o & 63;
        float aj = 0.f, ai = 0.f;
        for (int c = 0; c < 66; c++) {
            float ctv = sCT[p * 66 + c];
            aj = fmaf(ctv, Wg1[c * 64 + h], aj);
            ai = fmaf(ctv, Wg1[(66 + c) * 64 + h], ai);
        }
        sTj[p * 64 + h] = aj;
        sTi[p * 64 + h] = ai;
    }
    __syncthreads();

    const float twA = sTw[lane], twB = sTw[lane + 32];
    const float b2A = bg2[lane], b2B = bg2[lane + 32];
    const float b3A = bg3[lane], b3B = bg3[lane + 32];
    float gA = 0.f, gB = 0.f;
    float* hw = sH + warp * 256;   // [k*4 + s], k in 0..63, s in 0..3

    for (int it = 0; it < 20; it++) {
        const int base = it * 32 + warp * 4;
#pragma unroll
        for (int s = 0; s < 4; s++) {
            int pr = base + s;
            bool vld = pr < 625;
            int p = vld ? pr / 25 : 0, qq = vld ? pr % 25 : 0;
            hw[lane * 4 + s] = fmaxf(sTi[p * 64 + lane] + sTj[qq * 64 + lane] + twA, 0.f);
            hw[(lane + 32) * 4 + s] =
                fmaxf(sTi[p * 64 + lane + 32] + sTj[qq * 64 + lane + 32] + twB, 0.f);
        }
        __syncwarp();

        float a0[4], a1[4];
#pragma unroll
        for (int s = 0; s < 4; s++) { a0[s] = b2A; a1[s] = b2B; }
#pragma unroll 8
        for (int k = 0; k < 64; k++) {
            float w0 = sW2[k * 64 + lane], w1 = sW2[k * 64 + lane + 32];
            float4 hv = *(float4*)&hw[k * 4];
            a0[0] = fmaf(hv.x, w0, a0[0]); a1[0] = fmaf(hv.x, w1, a1[0]);
            a0[1] = fmaf(hv.y, w0, a0[1]); a1[1] = fmaf(hv.y, w1, a1[1]);
            a0[2] = fmaf(hv.z, w0, a0[2]); a1[2] = fmaf(hv.z, w1, a1[2]);
            a0[3] = fmaf(hv.w, w0, a0[3]); a1[3] = fmaf(hv.w, w1, a1[3]);
        }
        __syncwarp();
#pragma unroll
        for (int s = 0; s < 4; s++) {
            hw[lane * 4 + s] = fmaxf(a0[s], 0.f);
            hw[(lane + 32) * 4 + s] = fmaxf(a1[s], 0.f);
        }
        __syncwarp();

#pragma unroll
        for (int s = 0; s < 4; s++) { a0[s] = b3A; a1[s] = b3B; }
#pragma unroll 8
        for (int k = 0; k < 64; k++) {
            float w0 = sW3[k * 64 + lane], w1 = sW3[k * 64 + lane + 32];
            float4 hv = *(float4*)&hw[k * 4];
            a0[0] = fmaf(hv.x, w0, a0[0]); a1[0] = fmaf(hv.x, w1, a1[0]);
            a0[1] = fmaf(hv.y, w0, a0[1]); a1[1] = fmaf(hv.y, w1, a1[1]);
            a0[2] = fmaf(hv.z, w0, a0[2]); a1[2] = fmaf(hv.z, w1, a1[2]);
            a0[3] = fmaf(hv.w, w0, a0[3]); a1[3] = fmaf(hv.w, w1, a1[3]);
        }
#pragma unroll
        for (int s = 0; s < 4; s++) {
            if (base + s < 625) {
                gA += fmaxf(a0[s], 0.f);
                gB += fmaxf(a1[s], 0.f);
            }
        }
        __syncwarp();
    }
    sGp[warp * 64 + lane] = gA;
    sGp[warp * 64 + lane + 32] = gB;
    __syncthreads();
    if (tid < 64) {
        float s = 0.f;
#pragma unroll
        for (int w = 0; w < 8; w++) s += sGp[w * 64 + tid];
        gout[(size_t)b * 64 + tid] = s;
    }
}

__global__ void final_head_kernel(const float* __restrict__ lat,
                                  const float* __restrict__ Wf1, const float* __restrict__ bf1,
                                  const float* __restrict__ Wf2, const float* __restrict__ bf2,
                                  const float* __restrict__ Wf3, const float* __restrict__ bf3,
                                  float* __restrict__ out) {
    __shared__ float sh1[8][64];
    int tid = threadIdx.x, lane = tid & 31, warp = tid >> 5;
    int b = blockIdx.x * 8 + warp;
    float a0 = bf1[lane], a1 = bf1[lane + 32];
    const float* g0 = d_g0 + (size_t)b * 64;
    const float* g1 = d_g1 + (size_t)b * 64;
    const float* lr = lat + (size_t)b * 256;
    for (int k = 0; k < 64; k++) {
        float g = g0[k];
        a0 = fmaf(g, Wf1[k * 64 + lane], a0);
        a1 = fmaf(g, Wf1[k * 64 + lane + 32], a1);
    }
    for (int k = 0; k < 64; k++) {
        float g = g1[k];
        a0 = fmaf(g, Wf1[(64 + k) * 64 + lane], a0);
        a1 = fmaf(g, Wf1[(64 + k) * 64 + lane + 32], a1);
    }
    for (int k = 0; k < 256; k++) {
        float g = lr[k];
        a0 = fmaf(g, Wf1[(128 + k) * 64 + lane], a0);
        a1 = fmaf(g, Wf1[(128 + k) * 64 + lane + 32], a1);
    }
    sh1[warp][lane] = fmaxf(a0, 0.f);
    sh1[warp][lane + 32] = fmaxf(a1, 0.f);
    __syncwarp();
    float c = bf2[lane];
    for (int k = 0; k < 64; k++) c = fmaf(sh1[warp][k], Wf2[k * 32 + lane], c);
    c = fmaxf(c, 0.f);
    float v = c * Wf3[lane];
#pragma unroll
    for (int o = 16; o; o >>= 1) v += __shfl_down_sync(0xffffffffu, v, o);
    if (lane == 0) out[b] = v + bf3[0];
}

extern "C" void kernel_launch(void* const* d_in, const int* in_sizes, int n_in,
                              void* d_out, int out_size) {
    const float* x0 = (const float*)d_in[0];
    const float* x1 = (const float*)d_in[1];
    const float* lat = (const float*)d_in[2];
    const float* Wc1 = (const float*)d_in[3];
    const float* Wc2 = (const float*)d_in[4];
    const float* Wc3 = (const float*)d_in[5];
    const float* Wc4 = (const float*)d_in[6];
    const float* bng = (const float*)d_in[7];
    const float* bnb = (const float*)d_in[8];
    const float* Wg1 = (const float*)d_in[9];
    const float* bg1 = (const float*)d_in[10];
    const float* Wg2 = (const float*)d_in[11];
    const float* bg2 = (const float*)d_in[12];
    const float* Wg3 = (const float*)d_in[13];
    const float* bg3 = (const float*)d_in[14];
    const float* Wf1 = (const float*)d_in[15];
    const float* bf1 = (const float*)d_in[16];
    const float* Wf2 = (const float*)d_in[17];
    const float* bf2 = (const float*)d_in[18];
    const float* Wf3 = (const float*)d_in[19];
    const float* bf3 = (const float*)d_in[20];
    float* out = (float*)d_out;

    float *buf1, *buf2, *buf3, *buf4, *wt1, *wt2, *wt3, *wt4, *g0p, *g1p;
    cudaGetSymbolAddress((void**)&buf1, d_buf1);
    cudaGetSymbolAddress((void**)&buf2, d_buf2);
    cudaGetSymbolAddress((void**)&buf3, d_buf3);
    cudaGetSymbolAddress((void**)&buf4, d_buf4);
    cudaGetSymbolAddress((void**)&wt1, d_Wt1);
    cudaGetSymbolAddress((void**)&wt2, d_Wt2);
    cudaGetSymbolAddress((void**)&wt3, d_Wt3);
    cudaGetSymbolAddress((void**)&wt4, d_Wt4);
    cudaGetSymbolAddress((void**)&g0p, d_g0);
    cudaGetSymbolAddress((void**)&g1p, d_g1);

    const int REL_SMEM = 15668 * 4;
    cudaFuncSetAttribute(relation_kernel, cudaFuncAttributeMaxDynamicSharedMemorySize, REL_SMEM);

    zero_misc_kernel<<<1, 128>>>();
    prep_weights_kernel<<<144, 256>>>(Wc1, Wc2, Wc3, Wc4);
    att_sum_kernel<<<64, 512>>>(lat);

    for (int im = 0; im < 2; im++) {
        const float* x = im ? x1 : x0;
        float* gp = im ? g1p : g0p;
        conv1_kernel<<<10000, 256>>>(x, wt1, buf1);
        bn_finalize_kernel<<<1, 64>>>(bng, bnb, 0, 1.f / 640000.f);
        conv64_kernel<25, 25, 23, 23, 1><<<4232, 128>>>(buf1, wt2, buf2);
        bn_finalize_kernel<<<1, 64>>>(bng, bnb, 1, 1.f / 541696.f);
        conv64_kernel<23, 23, 11, 11, 2><<<968, 128>>>(buf2, wt3, buf3);
        bn_finalize_kernel<<<1, 64>>>(bng, bnb, 2, 1.f / 123904.f);
        conv64_kernel<11, 11, 5, 5, 2><<<200, 128>>>(buf3, wt4, buf4);
        bn_finalize_kernel<<<1, 64>>>(bng, bnb, 3, 1.f / 25600.f);
        relation_kernel<<<1024, 256, REL_SMEM>>>(buf4, lat, Wg1, bg1, Wg2, bg2,
                                                 Wg3, bg3, im, gp);
    }
    final_head_kernel<<<128, 256>>>(lat, Wf1, bf1, Wf2, bf2, Wf3, bf3, out);
}

// round 6
// speedup vs baseline: 1.2914x; 1.0156x over previous
#include <cuda_runtime.h>
#include <math.h>
#include <stdint.h>

// ---------------------------------------------------------------------------
// RelationNetworks forward. B=1024, C=64, L=64, H=64, IMG=27.
// conv chain: 27 ->(s1) 25 ->(s1) 23 ->(s2) 11 ->(s2) 5
// Activations NHWC [b][sp][c]. conv2/3/4 on tensor cores (3xTF32 mma.sync).
// ---------------------------------------------------------------------------

__device__ float d_buf1[1024 * 625 * 64];
__device__ float d_buf2[1024 * 529 * 64];
__device__ float d_buf3[1024 * 121 * 64];
__device__ float d_buf4[1024 * 25 * 64];
__device__ float d_Wt1[32 * 64];            // conv1 [k=(ky,kx,ic) pad32][oc]
__device__ uint32_t d_W2h[576 * 64], d_W2l[576 * 64];   // tf32 hi/lo splits
__device__ uint32_t d_W3h[576 * 64], d_W3l[576 * 64];
__device__ uint32_t d_W4h[576 * 64], d_W4l[576 * 64];
__device__ float d_statsA[8 * 128];         // per (im,layer): sum[64], sumsq[64]
__device__ float d_Ssum[2];                 // attention softmax denominators
__device__ float d_g0[1024 * 64];
__device__ float d_g1[1024 * 64];

// ---------------------------- helpers --------------------------------------
__device__ __forceinline__ uint32_t tf32_rna(float x) {
    uint32_t r;
    asm("cvt.rna.tf32.f32 %0, %1;" : "=r"(r) : "f"(x));
    return r;
}

__device__ __forceinline__ void mma_tf32(float c[4], const uint32_t a[4],
                                         const uint32_t b[2]) {
    asm volatile(
        "mma.sync.aligned.m16n8k8.row.col.f32.tf32.tf32.f32 "
        "{%0,%1,%2,%3}, {%4,%5,%6,%7}, {%8,%9}, {%0,%1,%2,%3};"
        : "+f"(c[0]), "+f"(c[1]), "+f"(c[2]), "+f"(c[3])
        : "r"(a[0]), "r"(a[1]), "r"(a[2]), "r"(a[3]), "r"(b[0]), "r"(b[1]));
}

// ---------------------------- small kernels --------------------------------
__global__ void zero_misc_kernel() {
    int t = threadIdx.x;
    if (t < 1024) d_statsA[t] = 0.f;
    if (t < 2) d_Ssum[t] = 0.f;
}

__global__ void prep_weights_kernel(const float* __restrict__ Wc1,
                                    const float* __restrict__ Wc2,
                                    const float* __restrict__ Wc3,
                                    const float* __restrict__ Wc4) {
    int i = blockIdx.x * blockDim.x + threadIdx.x;
    if (i < 32 * 64) {
        int k = i >> 6, oc = i & 63;
        d_Wt1[i] = (k < 27) ? Wc1[oc * 27 + (k % 3) * 9 + (k / 3)] : 0.f;
    }
    if (i < 576 * 64) {
        int k = i >> 6, oc = i & 63;
        int src = oc * 576 + (k & 63) * 9 + (k >> 6);
        float w2 = Wc2[src], w3 = Wc3[src], w4 = Wc4[src];
        uint32_t h;
        h = tf32_rna(w2); d_W2h[i] = h; d_W2l[i] = tf32_rna(w2 - __uint_as_float(h));
        h = tf32_rna(w3); d_W3h[i] = h; d_W3l[i] = tf32_rna(w3 - __uint_as_float(h));
        h = tf32_rna(w4); d_W4h[i] = h; d_W4l[i] = tf32_rna(w4 - __uint_as_float(h));
    }
}

__global__ void att_sum_kernel(const float* __restrict__ lat) {
    int i = blockIdx.x * blockDim.x + threadIdx.x;
    float p0 = 0.f, p1 = 0.f;
    for (int idx = i; idx < 65536; idx += gridDim.x * blockDim.x) {
        int b = idx >> 6, c = idx & 63;
        p0 += expf(lat[(b * 4 + 2) * 64 + c]);
        p1 += expf(lat[(b * 4 + 3) * 64 + c]);
    }
#pragma unroll
    for (int o = 16; o; o >>= 1) {
        p0 += __shfl_down_sync(0xffffffffu, p0, o);
        p1 += __shfl_down_sync(0xffffffffu, p1, o);
    }
    if ((threadIdx.x & 31) == 0) {
        atomicAdd(&d_Ssum[0], p0);
        atomicAdd(&d_Ssum[1], p1);
    }
}

// per-channel sum/sumsq of an NHWC buffer -> stats slot
__global__ void __launch_bounds__(256) stats_kernel(
    const float* __restrict__ buf, int rows, float* __restrict__ slot) {
    __shared__ float red[2][64][16];
    int tid = threadIdx.x;
    int c4 = tid & 15, j = tid >> 4;
    float4 s = make_float4(0.f, 0.f, 0.f, 0.f);
    float4 q = make_float4(0.f, 0.f, 0.f, 0.f);
    for (int r = blockIdx.x * 16 + j; r < rows; r += gridDim.x * 16) {
        float4 v = *(const float4*)(buf + (size_t)r * 64 + c4 * 4);
        s.x += v.x; s.y += v.y; s.z += v.z; s.w += v.w;
        q.x += v.x * v.x; q.y += v.y * v.y; q.z += v.z * v.z; q.w += v.w * v.w;
    }
    red[0][c4 * 4 + 0][j] = s.x; red[0][c4 * 4 + 1][j] = s.y;
    red[0][c4 * 4 + 2][j] = s.z; red[0][c4 * 4 + 3][j] = s.w;
    red[1][c4 * 4 + 0][j] = q.x; red[1][c4 * 4 + 1][j] = q.y;
    red[1][c4 * 4 + 2][j] = q.z; red[1][c4 * 4 + 3][j] = q.w;
    __syncthreads();
    if (tid < 128) {
        int si = tid >> 6, c = tid & 63;
        float v = 0.f;
#pragma unroll
        for (int t = 0; t < 16; t++) v += red[si][c][t];
        atomicAdd(&slot[si * 64 + c], v);
    }
}

// ---- conv1: NCHW input (3 ch), NHWC raw output. SIMT GEMM ----------------
__global__ void __launch_bounds__(256) conv1_kernel(
    const float* __restrict__ in, const float* __restrict__ Wt,
    float* __restrict__ out) {
    constexpr int BK = 16;
    __shared__ float As[BK][64];
    __shared__ float Bs[BK][64];

    const int tid = threadIdx.x;
    const int tx = tid & 15, ty = tid >> 4;
    const int m0 = blockIdx.x * 64;

    const int mi = tid >> 2;
    const int kb = (tid & 3) * 4;
    const int mg = m0 + mi;
    const int bI = mg / 625;
    const int sp = mg - bI * 625;
    const int oy = sp / 25;
    const int ox = sp - oy * 25;
    const float* inb = in + ((size_t)bI * 3) * 729 + oy * 27 + ox;

    float acc[4][4];
#pragma unroll
    for (int i = 0; i < 4; i++)
#pragma unroll
        for (int j = 0; j < 4; j++) acc[i][j] = 0.f;

    for (int k0 = 0; k0 < 32; k0 += BK) {
        {
            int ki = tid >> 4;
            int oc = (tid & 15) * 4;
            *(float4*)&Bs[ki][oc] = *(const float4*)(Wt + (k0 + ki) * 64 + oc);
        }
#pragma unroll
        for (int j = 0; j < 4; j++) {
            int k = k0 + kb + j;
            float v = 0.f;
            if (k < 27) {
                int w = k / 3, ic = k - w * 3;
                int ky = w / 3, kx = w - ky * 3;
                v = inb[ic * 729 + ky * 27 + kx];
            }
            As[kb + j][mi] = v;
        }
        __syncthreads();
#pragma unroll
        for (int kk = 0; kk < BK; kk++) {
            float4 a4 = *(float4*)&As[kk][ty * 4];
            float4 b4 = *(float4*)&Bs[kk][tx * 4];
            float av[4] = {a4.x, a4.y, a4.z, a4.w};
            float bw[4] = {b4.x, b4.y, b4.z, b4.w};
#pragma unroll
            for (int i = 0; i < 4; i++)
#pragma unroll
                for (int j = 0; j < 4; j++)
                    acc[i][j] = fmaf(av[i], bw[j], acc[i][j]);
        }
        __syncthreads();
    }
#pragma unroll
    for (int i = 0; i < 4; i++) {
        float4 v = make_float4(acc[i][0], acc[i][1], acc[i][2], acc[i][3]);
        *(float4*)(out + (size_t)(m0 + ty * 4 + i) * 64 + tx * 4) = v;
    }
}

// ---- conv64 tensor-core: 3xTF32 mma.sync, BM=128, BN=64, BK=16 ------------
// in: NHWC prev raw; BN scale/shift computed in-block from stats; out raw.
template <int IH, int IW, int OH, int OW, int STRIDE>
__global__ void __launch_bounds__(256) conv_tc_kernel(
    const float* __restrict__ in, const uint32_t* __restrict__ Wh,
    const uint32_t* __restrict__ Wl, float* __restrict__ out,
    const float* __restrict__ stats, const float* __restrict__ bn_g,
    const float* __restrict__ bn_b, float invN) {
    constexpr int OSP = OH * OW;
    __shared__ uint32_t Ah[16][136], Al[16][136];
    __shared__ uint32_t Bh[16][72], Bl[16][72];
    __shared__ float sBn[128];

    const int tid = threadIdx.x;
    const int lane = tid & 31, warp = tid >> 5;
    const int wm = warp & 3, wn = warp >> 2;
    const int lg = lane >> 2, lt = lane & 3;

    if (tid < 64) {
        float s = stats[tid], q = stats[64 + tid];
        float mean = s * invN;
        float var = q * invN - mean * mean;
        float sc = bn_g[tid] * rsqrtf(var + 1e-5f);
        sBn[tid] = sc;
        sBn[64 + tid] = bn_b[tid] - mean * sc;
    }

    const int row = tid & 127;
    const int khalf = (tid >> 7) * 8;
    const int mg = blockIdx.x * 128 + row;
    const int bI = mg / OSP;
    const int sp = mg - bI * OSP;
    const int oy = sp / OW;
    const int ox = sp - oy * OW;
    const float* inb = in + (((size_t)bI * IH + oy * STRIDE) * IW + ox * STRIDE) * 64;

    float c[2][4][4];
#pragma unroll
    for (int m = 0; m < 2; m++)
#pragma unroll
        for (int n = 0; n < 4; n++)
#pragma unroll
            for (int e = 0; e < 4; e++) c[m][n][e] = 0.f;

    __syncthreads();

#pragma unroll 1
    for (int k0 = 0; k0 < 576; k0 += 16) {
        const int w = k0 >> 6;
        const int ic0 = k0 & 63;
        const int ky = w / 3, kx = w - ky * 3;
        {   // B tile hi/lo (pre-split weights)
            int ki = tid >> 4, oc = (tid & 15) * 4;
            *(uint4*)&Bh[ki][oc] = *(const uint4*)(Wh + (size_t)(k0 + ki) * 64 + oc);
            *(uint4*)&Bl[ki][oc] = *(const uint4*)(Wl + (size_t)(k0 + ki) * 64 + oc);
        }
        {   // A tile: 8 ic for this row, fused BN+ReLU, split hi/lo
            const float* src = inb + (ky * IW + kx) * 64 + ic0 + khalf;
#pragma unroll
            for (int j = 0; j < 2; j++) {
                float4 v = *(const float4*)(src + j * 4);
                float xs[4] = {v.x, v.y, v.z, v.w};
#pragma unroll
                for (int e = 0; e < 4; e++) {
                    int ic = ic0 + khalf + j * 4 + e;
                    float x = fmaxf(fmaf(xs[e], sBn[ic], sBn[64 + ic]), 0.f);
                    uint32_t h = tf32_rna(x);
                    Ah[khalf + j * 4 + e][row] = h;
                    Al[khalf + j * 4 + e][row] = tf32_rna(x - __uint_as_float(h));
                }
            }
        }
        __syncthreads();
#pragma unroll
        for (int kk = 0; kk < 16; kk += 8) {
            uint32_t ah[2][4], al[2][4];
#pragma unroll
            for (int m = 0; m < 2; m++) {
                int rf = wm * 32 + m * 16 + lg;
                ah[m][0] = Ah[kk + lt][rf];
                ah[m][1] = Ah[kk + lt][rf + 8];
                ah[m][2] = Ah[kk + lt + 4][rf];
                ah[m][3] = Ah[kk + lt + 4][rf + 8];
                al[m][0] = Al[kk + lt][rf];
                al[m][1] = Al[kk + lt][rf + 8];
                al[m][2] = Al[kk + lt + 4][rf];
                al[m][3] = Al[kk + lt + 4][rf + 8];
            }
            uint32_t bh[4][2], bl[4][2];
#pragma unroll
            for (int n = 0; n < 4; n++) {
                int cf = wn * 32 + n * 8 + lg;
                bh[n][0] = Bh[kk + lt][cf];
                bh[n][1] = Bh[kk + lt + 4][cf];
                bl[n][0] = Bl[kk + lt][cf];
                bl[n][1] = Bl[kk + lt + 4][cf];
            }
#pragma unroll
            for (int m = 0; m < 2; m++)
#pragma unroll
                for (int n = 0; n < 4; n++) {
                    mma_tf32(c[m][n], ah[m], bh[n]);
                    mma_tf32(c[m][n], ah[m], bl[n]);
                    mma_tf32(c[m][n], al[m], bh[n]);
                }
        }
        __syncthreads();
    }

    // store raw NHWC
#pragma unroll
    for (int m = 0; m < 2; m++) {
        int r = blockIdx.x * 128 + wm * 32 + m * 16 + lg;
#pragma unroll
        for (int n = 0; n < 4; n++) {
            int col = wn * 32 + n * 8 + lt * 2;
            float2 v0 = make_float2(c[m][n][0], c[m][n][1]);
            float2 v1 = make_float2(c[m][n][2], c[m][n][3]);
            *(float2*)(out + (size_t)r * 64 + col) = v0;
            *(float2*)(out + (size_t)(r + 8) * 64 + col) = v1;
        }
    }
}

// ---- relation network: one block per batch element ------------------------
__global__ void __launch_bounds__(256) relation_kernel(
    const float* __restrict__ conv4, const float* __restrict__ lat,
    const float* __restrict__ Wg1, const float* __restrict__ bg1,
    const float* __restrict__ Wg2, const float* __restrict__ bg2,
    const float* __restrict__ Wg3, const float* __restrict__ bg3,
    const float* __restrict__ stats, const float* __restrict__ bn_g,
    const float* __restrict__ bn_b, float invN,
    int im, float* __restrict__ gout) {
    extern __shared__ float sm[];
    float* sW2 = sm;              // 4096
    float* sW3 = sm + 4096;       // 4096
    float* sTi = sm + 8192;       // 1600
    float* sTj = sm + 9792;       // 1600
    float* sCT = sm + 11392;      // 1650
    float* sTw = sm + 13042;      // 64
    float* sH  = sm + 13108;      // 8 warps * 256 (16B aligned)
    float* sGp = sm + 15156;      // 8 * 64 -> total 15668 floats
    __shared__ float sBn[128];

    const int tid = threadIdx.x;
    const int b = blockIdx.x;
    const int lane = tid & 31, warp = tid >> 5;

    if (tid < 64) {
        float s = stats[tid], q = stats[64 + tid];
        float mean = s * invN;
        float var = q * invN - mean * mean;
        float sc = bn_g[tid] * rsqrtf(var + 1e-5f);
        sBn[tid] = sc;
        sBn[64 + tid] = bn_b[tid] - mean * sc;
    }
    for (int i = tid; i < 4096; i += 256) {
        sW2[i] = Wg2[i];
        sW3[i] = Wg3[i];
    }
    __syncthreads();

    const float invS = 1.f / (d_Ssum[im] + 1e-9f);
    const float* aRow = lat + ((size_t)b * 4 + 2 + im) * 64;
    const float* wRow = lat + ((size_t)b * 4 + im) * 64;

    for (int i = tid; i < 1600; i += 256) {
        int p = i >> 6, cc = i & 63;
        float v = conv4[((size_t)b * 25 + p) * 64 + cc];
        v = fmaxf(fmaf(v, sBn[cc], sBn[64 + cc]), 0.f);
        v *= expf(aRow[cc]) * invS;
        sCT[p * 66 + cc] = v;
    }
    if (tid < 50) {
        int p = tid % 25, cc = tid / 25;
        sCT[p * 66 + 64 + cc] = (cc == 0) ? (float)(p % 5) - 2.f : (float)(p / 5) - 2.f;
    }
    if (tid < 64) {
        float acc = bg1[tid];
        for (int cc = 0; cc < 64; cc++)
            acc = fmaf(wRow[cc], Wg1[(132 + cc) * 64 + tid], acc);
        sTw[tid] = acc;
    }
    __syncthreads();

    for (int o = tid; o < 1600; o += 256) {
        int p = o >> 6, h = o & 63;
        float aj = 0.f, ai = 0.f;
        for (int cc = 0; cc < 66; cc++) {
            float ctv = sCT[p * 66 + cc];
            aj = fmaf(ctv, Wg1[cc * 64 + h], aj);
            ai = fmaf(ctv, Wg1[(66 + cc) * 64 + h], ai);
        }
        sTj[p * 64 + h] = aj;
        sTi[p * 64 + h] = ai;
    }
    __syncthreads();

    const float twA = sTw[lane], twB = sTw[lane + 32];
    const float b2A = bg2[lane], b2B = bg2[lane + 32];
    const float b3A = bg3[lane], b3B = bg3[lane + 32];
    float gA = 0.f, gB = 0.f;
    float* hw = sH + warp * 256;   // [k*4 + s]

    for (int it = 0; it < 20; it++) {
        const int base = it * 32 + warp * 4;
#pragma unroll
        for (int s = 0; s < 4; s++) {
            int pr = base + s;
            bool vld = pr < 625;
            int p = vld ? pr / 25 : 0, qq = vld ? pr % 25 : 0;
            hw[lane * 4 + s] = fmaxf(sTi[p * 64 + lane] + sTj[qq * 64 + lane] + twA, 0.f);
            hw[(lane + 32) * 4 + s] =
                fmaxf(sTi[p * 64 + lane + 32] + sTj[qq * 64 + lane + 32] + twB, 0.f);
        }
        __syncwarp();

        float a0[4], a1[4];
#pragma unroll
        for (int s = 0; s < 4; s++) { a0[s] = b2A; a1[s] = b2B; }
#pragma unroll 8
        for (int k = 0; k < 64; k++) {
            float w0 = sW2[k * 64 + lane], w1 = sW2[k * 64 + lane + 32];
            float4 hv = *(float4*)&hw[k * 4];
            a0[0] = fmaf(hv.x, w0, a0[0]); a1[0] = fmaf(hv.x, w1, a1[0]);
            a0[1] = fmaf(hv.y, w0, a0[1]); a1[1] = fmaf(hv.y, w1, a1[1]);
            a0[2] = fmaf(hv.z, w0, a0[2]); a1[2] = fmaf(hv.z, w1, a1[2]);
            a0[3] = fmaf(hv.w, w0, a0[3]); a1[3] = fmaf(hv.w, w1, a1[3]);
        }
        __syncwarp();
#pragma unroll
        for (int s = 0; s < 4; s++) {
            hw[lane * 4 + s] = fmaxf(a0[s], 0.f);
            hw[(lane + 32) * 4 + s] = fmaxf(a1[s], 0.f);
        }
        __syncwarp();

#pragma unroll
        for (int s = 0; s < 4; s++) { a0[s] = b3A; a1[s] = b3B; }
#pragma unroll 8
        for (int k = 0; k < 64; k++) {
            float w0 = sW3[k * 64 + lane], w1 = sW3[k * 64 + lane + 32];
            float4 hv = *(float4*)&hw[k * 4];
            a0[0] = fmaf(hv.x, w0, a0[0]); a1[0] = fmaf(hv.x, w1, a1[0]);
            a0[1] = fmaf(hv.y, w0, a0[1]); a1[1] = fmaf(hv.y, w1, a1[1]);
            a0[2] = fmaf(hv.z, w0, a0[2]); a1[2] = fmaf(hv.z, w1, a1[2]);
            a0[3] = fmaf(hv.w, w0, a0[3]); a1[3] = fmaf(hv.w, w1, a1[3]);
        }
#pragma unroll
        for (int s = 0; s < 4; s++) {
            if (base + s < 625) {
                gA += fmaxf(a0[s], 0.f);
                gB += fmaxf(a1[s], 0.f);
            }
        }
        __syncwarp();
    }
    sGp[warp * 64 + lane] = gA;
    sGp[warp * 64 + lane + 32] = gB;
    __syncthreads();
    if (tid < 64) {
        float s = 0.f;
#pragma unroll
        for (int w = 0; w < 8; w++) s += sGp[w * 64 + tid];
        gout[(size_t)b * 64 + tid] = s;
    }
}

__global__ void final_head_kernel(const float* __restrict__ lat,
                                  const float* __restrict__ Wf1, const float* __restrict__ bf1,
                                  const float* __restrict__ Wf2, const float* __restrict__ bf2,
                                  const float* __restrict__ Wf3, const float* __restrict__ bf3,
                                  float* __restrict__ out) {
    __shared__ float sh1[8][64];
    int tid = threadIdx.x, lane = tid & 31, warp = tid >> 5;
    int b = blockIdx.x * 8 + warp;
    float a0 = bf1[lane], a1 = bf1[lane + 32];
    const float* g0 = d_g0 + (size_t)b * 64;
    const float* g1 = d_g1 + (size_t)b * 64;
    const float* lr = lat + (size_t)b * 256;
    for (int k = 0; k < 64; k++) {
        float g = g0[k];
        a0 = fmaf(g, Wf1[k * 64 + lane], a0);
        a1 = fmaf(g, Wf1[k * 64 + lane + 32], a1);
    }
    for (int k = 0; k < 64; k++) {
        float g = g1[k];
        a0 = fmaf(g, Wf1[(64 + k) * 64 + lane], a0);
        a1 = fmaf(g, Wf1[(64 + k) * 64 + lane + 32], a1);
    }
    for (int k = 0; k < 256; k++) {
        float g = lr[k];
        a0 = fmaf(g, Wf1[(128 + k) * 64 + lane], a0);
        a1 = fmaf(g, Wf1[(128 + k) * 64 + lane + 32], a1);
    }
    sh1[warp][lane] = fmaxf(a0, 0.f);
    sh1[warp][lane + 32] = fmaxf(a1, 0.f);
    __syncwarp();
    float c = bf2[lane];
    for (int k = 0; k < 64; k++) c = fmaf(sh1[warp][k], Wf2[k * 32 + lane], c);
    c = fmaxf(c, 0.f);
    float v = c * Wf3[lane];
#pragma unroll
    for (int o = 16; o; o >>= 1) v += __shfl_down_sync(0xffffffffu, v, o);
    if (lane == 0) out[b] = v + bf3[0];
}

extern "C" void kernel_launch(void* const* d_in, const int* in_sizes, int n_in,
                              void* d_out, int out_size) {
    const float* x0 = (const float*)d_in[0];
    const float* x1 = (const float*)d_in[1];
    const float* lat = (const float*)d_in[2];
    const float* Wc1 = (const float*)d_in[3];
    const float* Wc2 = (const float*)d_in[4];
    const float* Wc3 = (const float*)d_in[5];
    const float* Wc4 = (const float*)d_in[6];
    const float* bng = (const float*)d_in[7];
    const float* bnb = (const float*)d_in[8];
    const float* Wg1 = (const float*)d_in[9];
    const float* bg1 = (const float*)d_in[10];
    const float* Wg2 = (const float*)d_in[11];
    const float* bg2 = (const float*)d_in[12];
    const float* Wg3 = (const float*)d_in[13];
    const float* bg3 = (const float*)d_in[14];
    const float* Wf1 = (const float*)d_in[15];
    const float* bf1 = (const float*)d_in[16];
    const float* Wf2 = (const float*)d_in[17];
    const float* bf2 = (const float*)d_in[18];
    const float* Wf3 = (const float*)d_in[19];
    const float* bf3 = (const float*)d_in[20];
    float* out = (float*)d_out;

    float *buf1, *buf2, *buf3, *buf4, *wt1, *statsA, *g0p, *g1p;
    uint32_t *w2h, *w2l, *w3h, *w3l, *w4h, *w4l;
    cudaGetSymbolAddress((void**)&buf1, d_buf1);
    cudaGetSymbolAddress((void**)&buf2, d_buf2);
    cudaGetSymbolAddress((void**)&buf3, d_buf3);
    cudaGetSymbolAddress((void**)&buf4, d_buf4);
    cudaGetSymbolAddress((void**)&wt1, d_Wt1);
    cudaGetSymbolAddress((void**)&w2h, d_W2h);
    cudaGetSymbolAddress((void**)&w2l, d_W2l);
    cudaGetSymbolAddress((void**)&w3h, d_W3h);
    cudaGetSymbolAddress((void**)&w3l, d_W3l);
    cudaGetSymbolAddress((void**)&w4h, d_W4h);
    cudaGetSymbolAddress((void**)&w4l, d_W4l);
    cudaGetSymbolAddress((void**)&statsA, d_statsA);
    cudaGetSymbolAddress((void**)&g0p, d_g0);
    cudaGetSymbolAddress((void**)&g1p, d_g1);

    const int REL_SMEM = 15668 * 4;
    cudaFuncSetAttribute(relation_kernel, cudaFuncAttributeMaxDynamicSharedMemorySize, REL_SMEM);

    zero_misc_kernel<<<1, 1024>>>();
    prep_weights_kernel<<<144, 256>>>(Wc1, Wc2, Wc3, Wc4);
    att_sum_kernel<<<64, 512>>>(lat);

    for (int im = 0; im < 2; im++) {
        const float* x = im ? x1 : x0;
        float* gp = im ? g1p : g0p;
        float* sl = statsA + im * 4 * 128;

        conv1_kernel<<<10000, 256>>>(x, wt1, buf1);
        stats_kernel<<<256, 256>>>(buf1, 640000, sl + 0 * 128);
        conv_tc_kernel<25, 25, 23, 23, 1><<<4232, 256>>>(
            buf1, w2h, w2l, buf2, sl + 0 * 128, bng + 0, bnb + 0, 1.f / 640000.f);
        stats_kernel<<<256, 256>>>(buf2, 541696, sl + 1 * 128);
        conv_tc_kernel<23, 23, 11, 11, 2><<<968, 256>>>(
            buf2, w3h, w3l, buf3, sl + 1 * 128, bng + 64, bnb + 64, 1.f / 541696.f);
        stats_kernel<<<256, 256>>>(buf3, 123904, sl + 2 * 128);
        conv_tc_kernel<11, 11, 5, 5, 2><<<200, 256>>>(
            buf3, w4h, w4l, buf4, sl + 2 * 128, bng + 128, bnb + 128, 1.f / 123904.f);
        stats_kernel<<<256, 256>>>(buf4, 25600, sl + 3 * 128);
        relation_kernel<<<1024, 256, REL_SMEM>>>(
            buf4, lat, Wg1, bg1, Wg2, bg2, Wg3, bg3,
            sl + 3 * 128, bng + 192, bnb + 192, 1.f / 25600.f, im, gp);
    }
    final_head_kernel<<<128, 256>>>(lat, Wf1, bf1, Wf2, bf2, Wf3, bf3, out);
}

// round 8
// speedup vs baseline: 1.4428x; 1.1172x over previous
#include <cuda_runtime.h>
#include <math.h>
#include <stdint.h>

// ---------------------------------------------------------------------------
// RelationNetworks forward. B=1024, C=64, L=64, H=64, IMG=27.
// conv chain: 27 ->(s1) 25 ->(s1) 23 ->(s2) 11 ->(s2) 5
// Activations NHWC [b][sp][c]. conv2/3/4 via mma.sync 3xTF32, reg accum.
// ---------------------------------------------------------------------------

__device__ float d_buf1[1024 * 625 * 64];
__device__ float d_buf2[1024 * 529 * 64];
__device__ float d_buf3[1024 * 121 * 64];
__device__ float d_buf4[1024 * 25 * 64];
__device__ float d_Wt1[32 * 64];          // conv1 [k pad32][oc]
// fragment-major packed weights: idx=(((c*2+wn)*4+nf)*4+ks)*32+lane ->
//   {hi(k0), hi(k0+4), lo(k0), lo(k0+4)}
__device__ uint4 d_Wf2[18432];
__device__ uint4 d_Wf3[18432];
__device__ uint4 d_Wf4[18432];
__device__ float d_statsA[8 * 128];
__device__ float d_Ssum[2];
__device__ float d_g0[1024 * 64];
__device__ float d_g1[1024 * 64];

// ---------------------------- helpers --------------------------------------
__device__ __forceinline__ uint32_t tf32_rna(float x) {
    uint32_t r;
    asm("cvt.rna.tf32.f32 %0, %1;" : "=r"(r) : "f"(x));
    return r;
}

__device__ __forceinline__ void mma_tf32(float c[4], const uint32_t a[4],
                                         uint32_t b0, uint32_t b1) {
    asm volatile(
        "mma.sync.aligned.m16n8k8.row.col.f32.tf32.tf32.f32 "
        "{%0,%1,%2,%3}, {%4,%5,%6,%7}, {%8,%9}, {%0,%1,%2,%3};"
        : "+f"(c[0]), "+f"(c[1]), "+f"(c[2]), "+f"(c[3])
        : "r"(a[0]), "r"(a[1]), "r"(a[2]), "r"(a[3]), "r"(b0), "r"(b1));
}

// ---------------------------- small kernels --------------------------------
__global__ void zero_misc_kernel() {
    int t = threadIdx.x;
    if (t < 1024) d_statsA[t] = 0.f;
    if (t < 2) d_Ssum[t] = 0.f;
}

// conv1 weight transpose + fragment-major tf32 hi/lo packing for conv2/3/4
__global__ void prep_weights_kernel(const float* __restrict__ Wc1,
                                    const float* __restrict__ Wc2,
                                    const float* __restrict__ Wc3,
                                    const float* __restrict__ Wc4) {
    int i = blockIdx.x * blockDim.x + threadIdx.x;
    if (i < 32 * 64) {
        int k = i >> 6, oc = i & 63;
        d_Wt1[i] = (k < 27) ? Wc1[oc * 27 + (k % 3) * 9 + (k / 3)] : 0.f;
    }
    if (i < 18432) {
        int l = i & 31;
        int ks = (i >> 5) & 3;
        int nf = (i >> 7) & 3;
        int wn = (i >> 9) & 1;
        int c = i >> 10;                     // 0..17
        int n = wn * 32 + nf * 8 + (l >> 2);
        int t = l & 3;
        int k0 = c * 32 + ks * 8 + t;        // global k; k1 = k0+4
        int ic0 = k0 & 63, w0 = k0 >> 6;
        int ic1 = (k0 + 4) & 63, w1 = (k0 + 4) >> 6;
        int s0 = n * 576 + ic0 * 9 + w0;
        int s1 = n * 576 + ic1 * 9 + w1;
        const float* Ws[3] = {Wc2, Wc3, Wc4};
        uint4* Wd[3] = {d_Wf2, d_Wf3, d_Wf4};
#pragma unroll
        for (int L = 0; L < 3; L++) {
            float v0 = Ws[L][s0], v1 = Ws[L][s1];
            uint32_t h0 = tf32_rna(v0), h1 = tf32_rna(v1);
            uint32_t l0 = tf32_rna(v0 - __uint_as_float(h0));
            uint32_t l1 = tf32_rna(v1 - __uint_as_float(h1));
            Wd[L][i] = make_uint4(h0, h1, l0, l1);
        }
    }
}

__global__ void att_sum_kernel(const float* __restrict__ lat) {
    int i = blockIdx.x * blockDim.x + threadIdx.x;
    float p0 = 0.f, p1 = 0.f;
    for (int idx = i; idx < 65536; idx += gridDim.x * blockDim.x) {
        int b = idx >> 6, c = idx & 63;
        p0 += expf(lat[(b * 4 + 2) * 64 + c]);
        p1 += expf(lat[(b * 4 + 3) * 64 + c]);
    }
#pragma unroll
    for (int o = 16; o; o >>= 1) {
        p0 += __shfl_down_sync(0xffffffffu, p0, o);
        p1 += __shfl_down_sync(0xffffffffu, p1, o);
    }
    if ((threadIdx.x & 31) == 0) {
        atomicAdd(&d_Ssum[0], p0);
        atomicAdd(&d_Ssum[1], p1);
    }
}

__global__ void __launch_bounds__(256) stats_kernel(
    const float* __restrict__ buf, int rows, float* __restrict__ slot) {
    __shared__ float red[2][64][16];
    int tid = threadIdx.x;
    int c4 = tid & 15, j = tid >> 4;
    float4 s = make_float4(0.f, 0.f, 0.f, 0.f);
    float4 q = make_float4(0.f, 0.f, 0.f, 0.f);
    for (int r = blockIdx.x * 16 + j; r < rows; r += gridDim.x * 16) {
        float4 v = *(const float4*)(buf + (size_t)r * 64 + c4 * 4);
        s.x += v.x; s.y += v.y; s.z += v.z; s.w += v.w;
        q.x += v.x * v.x; q.y += v.y * v.y; q.z += v.z * v.z; q.w += v.w * v.w;
    }
    red[0][c4 * 4 + 0][j] = s.x; red[0][c4 * 4 + 1][j] = s.y;
    red[0][c4 * 4 + 2][j] = s.z; red[0][c4 * 4 + 3][j] = s.w;
    red[1][c4 * 4 + 0][j] = q.x; red[1][c4 * 4 + 1][j] = q.y;
    red[1][c4 * 4 + 2][j] = q.z; red[1][c4 * 4 + 3][j] = q.w;
    __syncthreads();
    if (tid < 128) {
        int si = tid >> 6, c = tid & 63;
        float v = 0.f;
#pragma unroll
        for (int t = 0; t < 16; t++) v += red[si][c][t];
        atomicAdd(&slot[si * 64 + c], v);
    }
}

// ---- conv1: NCHW input (3 ch), NHWC raw output. SIMT GEMM ----------------
__global__ void __launch_bounds__(256) conv1_kernel(
    const float* __restrict__ in, const float* __restrict__ Wt,
    float* __restrict__ out) {
    constexpr int BK = 16;
    __shared__ float As[BK][64];
    __shared__ float Bs[BK][64];

    const int tid = threadIdx.x;
    const int tx = tid & 15, ty = tid >> 4;
    const int m0 = blockIdx.x * 64;

    const int mi = tid >> 2;
    const int kb = (tid & 3) * 4;
    const int mg = m0 + mi;
    const int bI = mg / 625;
    const int sp = mg - bI * 625;
    const int oy = sp / 25;
    const int ox = sp - oy * 25;
    const float* inb = in + ((size_t)bI * 3) * 729 + oy * 27 + ox;

    float acc[4][4];
#pragma unroll
    for (int i = 0; i < 4; i++)
#pragma unroll
        for (int j = 0; j < 4; j++) acc[i][j] = 0.f;

    for (int k0 = 0; k0 < 32; k0 += BK) {
        {
            int ki = tid >> 4;
            int oc = (tid & 15) * 4;
            *(float4*)&Bs[ki][oc] = *(const float4*)(Wt + (k0 + ki) * 64 + oc);
        }
#pragma unroll
        for (int j = 0; j < 4; j++) {
            int k = k0 + kb + j;
            float v = 0.f;
            if (k < 27) {
                int w = k / 3, ic = k - w * 3;
                int ky = w / 3, kx = w - ky * 3;
                v = inb[ic * 729 + ky * 27 + kx];
            }
            As[kb + j][mi] = v;
        }
        __syncthreads();
#pragma unroll
        for (int kk = 0; kk < BK; kk++) {
            float4 a4 = *(float4*)&As[kk][ty * 4];
            float4 b4 = *(float4*)&Bs[kk][tx * 4];
            float av[4] = {a4.x, a4.y, a4.z, a4.w};
            float bw[4] = {b4.x, b4.y, b4.z, b4.w};
#pragma unroll
            for (int i = 0; i < 4; i++)
#pragma unroll
                for (int j = 0; j < 4; j++)
                    acc[i][j] = fmaf(av[i], bw[j], acc[i][j]);
        }
        __syncthreads();
    }
#pragma unroll
    for (int i = 0; i < 4; i++) {
        float4 v = make_float4(acc[i][0], acc[i][1], acc[i][2], acc[i][3]);
        *(float4*)(out + (size_t)(m0 + ty * 4 + i) * 64 + tx * 4) = v;
    }
}

// ---- conv64 via mma.sync 3xTF32: BM=128, BN=64, BK=32, double-buffered ----
// A smem [k 32][row pad136] hi+lo; B fragment-major from gmem (L1-resident).
template <int IH, int IW, int OH, int OW, int STRIDE>
__global__ void __launch_bounds__(256) conv_mma3_kernel(
    const float* __restrict__ in, const uint4* __restrict__ Wf,
    float* __restrict__ out,
    const float* __restrict__ stats, const float* __restrict__ bn_g,
    const float* __restrict__ bn_b, float invN) {
    constexpr int OSP = OH * OW;
    constexpr int STG = 2 * 32 * 136;        // floats per stage (hi+lo)
    extern __shared__ float sm[];
    __shared__ float sBn[128];

    const int tid = threadIdx.x;
    const int lane = tid & 31, warp = tid >> 5;
    const int wm = warp & 3, wn = warp >> 2;
    const int lg = lane >> 2, lt = lane & 3;

    if (tid < 64) {
        float s = stats[tid], q = stats[64 + tid];
        float mean = s * invN;
        float var = q * invN - mean * mean;
        float sc = bn_g[tid] * rsqrtf(var + 1e-5f);
        sBn[tid] = sc;
        sBn[64 + tid] = bn_b[tid] - mean * sc;
    }

    // producer coords: one row per 2 threads, 16 k each
    const int row = tid >> 1;
    const int khalf = tid & 1;
    const int mg = blockIdx.x * 128 + row;
    const int bI = mg / OSP;
    const int sp = mg - bI * OSP;
    const int oy = sp / OW;
    const int ox = sp - oy * OW;
    const float* inb = in + (((size_t)bI * IH + oy * STRIDE) * IW + ox * STRIDE) * 64;

    float c[2][4][4];
#pragma unroll
    for (int m = 0; m < 2; m++)
#pragma unroll
        for (int n = 0; n < 4; n++)
#pragma unroll
            for (int e = 0; e < 4; e++) c[m][n][e] = 0.f;

    __syncthreads();

    // fill chunk into stage s
    auto fill = [&](int s, int ch) {
        const int w = ch >> 1;
        const int ic0 = (ch & 1) * 32;
        const int ky = w / 3, kx = w - ky * 3;
        float* aH = sm + s * STG;
        float* aL = aH + 32 * 136;
        const float* src = inb + (ky * IW + kx) * 64 + ic0 + khalf * 16;
#pragma unroll
        for (int j = 0; j < 4; j++) {
            float4 v = *(const float4*)(src + j * 4);
            int icb = ic0 + khalf * 16 + j * 4;
            float4 sc = *(const float4*)&sBn[icb];
            float4 sh = *(const float4*)&sBn[64 + icb];
            float xs[4] = {fmaxf(fmaf(v.x, sc.x, sh.x), 0.f),
                           fmaxf(fmaf(v.y, sc.y, sh.y), 0.f),
                           fmaxf(fmaf(v.z, sc.z, sh.z), 0.f),
                           fmaxf(fmaf(v.w, sc.w, sh.w), 0.f)};
            int kl = khalf * 16 + j * 4;
#pragma unroll
            for (int e = 0; e < 4; e++) {
                uint32_t h = tf32_rna(xs[e]);
                uint32_t l = tf32_rna(xs[e] - __uint_as_float(h));
                aH[(kl + e) * 136 + row] = __uint_as_float(h);
                aL[(kl + e) * 136 + row] = __uint_as_float(l);
            }
        }
    };

    fill(0, 0);
    __syncthreads();

#pragma unroll 1
    for (int ch = 0; ch < 18; ch++) {
        if (ch + 1 < 18) fill((ch + 1) & 1, ch + 1);

        const float* aH = sm + (ch & 1) * STG;
        const float* aL = aH + 32 * 136;
        const uint4* wp = Wf + ((ch * 2 + wn) * 4) * 4 * 32 + lane;
#pragma unroll
        for (int ks = 0; ks < 4; ks++) {
            uint32_t ah[2][4], al[2][4];
#pragma unroll
            for (int m = 0; m < 2; m++) {
                int rf = wm * 32 + m * 16 + lg;
                int kb = ks * 8 + lt;
                ah[m][0] = __float_as_uint(aH[kb * 136 + rf]);
                ah[m][1] = __float_as_uint(aH[kb * 136 + rf + 8]);
                ah[m][2] = __float_as_uint(aH[(kb + 4) * 136 + rf]);
                ah[m][3] = __float_as_uint(aH[(kb + 4) * 136 + rf + 8]);
                al[m][0] = __float_as_uint(aL[kb * 136 + rf]);
                al[m][1] = __float_as_uint(aL[kb * 136 + rf + 8]);
                al[m][2] = __float_as_uint(aL[(kb + 4) * 136 + rf]);
                al[m][3] = __float_as_uint(aL[(kb + 4) * 136 + rf + 8]);
            }
#pragma unroll
            for (int nf = 0; nf < 4; nf++) {
                uint4 b = wp[(nf * 4 + ks) * 32];
#pragma unroll
                for (int m = 0; m < 2; m++) {
                    mma_tf32(c[m][nf], ah[m], b.x, b.y);   // hi*hi
                    mma_tf32(c[m][nf], ah[m], b.z, b.w);   // hi*lo
                    mma_tf32(c[m][nf], al[m], b.x, b.y);   // lo*hi
                }
            }
        }
        __syncthreads();
    }

    // epilogue: raw NHWC stores (mapping validated in round 6)
#pragma unroll
    for (int m = 0; m < 2; m++) {
        int r = blockIdx.x * 128 + wm * 32 + m * 16 + lg;
#pragma unroll
        for (int nf = 0; nf < 4; nf++) {
            int col = wn * 32 + nf * 8 + lt * 2;
            *(float2*)(out + (size_t)r * 64 + col) =
                make_float2(c[m][nf][0], c[m][nf][1]);
            *(float2*)(out + (size_t)(r + 8) * 64 + col) =
                make_float2(c[m][nf][2], c[m][nf][3]);
        }
    }
}

// ---- relation network: one block per batch element ------------------------
__global__ void __launch_bounds__(256) relation_kernel(
    const float* __restrict__ conv4, const float* __restrict__ lat,
    const float* __restrict__ Wg1, const float* __restrict__ bg1,
    const float* __restrict__ Wg2, const float* __restrict__ bg2,
    const float* __restrict__ Wg3, const float* __restrict__ bg3,
    const float* __restrict__ stats, const float* __restrict__ bn_g,
    const float* __restrict__ bn_b, float invN,
    int im, float* __restrict__ gout) {
    extern __shared__ float sm[];
    float* sW2 = sm;
    float* sW3 = sm + 4096;
    float* sTi = sm + 8192;
    float* sTj = sm + 9792;
    float* sCT = sm + 11392;
    float* sTw = sm + 13042;
    float* sH  = sm + 13108;
    float* sGp = sm + 15156;
    __shared__ float sBn[128];

    const int tid = threadIdx.x;
    const int b = blockIdx.x;
    const int lane = tid & 31, warp = tid >> 5;

    if (tid < 64) {
        float s = stats[tid], q = stats[64 + tid];
        float mean = s * invN;
        float var = q * invN - mean * mean;
        float sc = bn_g[tid] * rsqrtf(var + 1e-5f);
        sBn[tid] = sc;
        sBn[64 + tid] = bn_b[tid] - mean * sc;
    }
    for (int i = tid; i < 4096; i += 256) {
        sW2[i] = Wg2[i];
        sW3[i] = Wg3[i];
    }
    __syncthreads();

    const float invS = 1.f / (d_Ssum[im] + 1e-9f);
    const float* aRow = lat + ((size_t)b * 4 + 2 + im) * 64;
    const float* wRow = lat + ((size_t)b * 4 + im) * 64;

    for (int i = tid; i < 1600; i += 256) {
        int p = i >> 6, cc = i & 63;
        float v = conv4[((size_t)b * 25 + p) * 64 + cc];
        v = fmaxf(fmaf(v, sBn[cc], sBn[64 + cc]), 0.f);
        v *= expf(aRow[cc]) * invS;
        sCT[p * 66 + cc] = v;
    }
    if (tid < 50) {
        int p = tid % 25, cc = tid / 25;
        sCT[p * 66 + 64 + cc] = (cc == 0) ? (float)(p % 5) - 2.f : (float)(p / 5) - 2.f;
    }
    if (tid < 64) {
        float acc = bg1[tid];
        for (int cc = 0; cc < 64; cc++)
            acc = fmaf(wRow[cc], Wg1[(132 + cc) * 64 + tid], acc);
        sTw[tid] = acc;
    }
    __syncthreads();

    for (int o = tid; o < 1600; o += 256) {
        int p = o >> 6, h = o & 63;
        float aj = 0.f, ai = 0.f;
        for (int cc = 0; cc < 66; cc++) {
            float ctv = sCT[p * 66 + cc];
            aj = fmaf(ctv, Wg1[cc * 64 + h], aj);
            ai = fmaf(ctv, Wg1[(66 + cc) * 64 + h], ai);
        }
        sTj[p * 64 + h] = aj;
        sTi[p * 64 + h] = ai;
    }
    __syncthreads();

    const float twA = sTw[lane], twB = sTw[lane + 32];
    const float b2A = bg2[lane], b2B = bg2[lane + 32];
    const float b3A = bg3[lane], b3B = bg3[lane + 32];
    float gA = 0.f, gB = 0.f;
    float* hw = sH + warp * 256;

    for (int it = 0; it < 20; it++) {
        const int base = it * 32 + warp * 4;
#pragma unroll
        for (int s = 0; s < 4; s++) {
            int pr = base + s;
            bool vld = pr < 625;
            int p = vld ? pr / 25 : 0, qq = vld ? pr % 25 : 0;
            hw[lane * 4 + s] = fmaxf(sTi[p * 64 + lane] + sTj[qq * 64 + lane] + twA, 0.f);
            hw[(lane + 32) * 4 + s] =
                fmaxf(sTi[p * 64 + lane + 32] + sTj[qq * 64 + lane + 32] + twB, 0.f);
        }
        __syncwarp();

        float a0[4], a1[4];
#pragma unroll
        for (int s = 0; s < 4; s++) { a0[s] = b2A; a1[s] = b2B; }
#pragma unroll 8
        for (int k = 0; k < 64; k++) {
            float w0 = sW2[k * 64 + lane], w1 = sW2[k * 64 + lane + 32];
            float4 hv = *(float4*)&hw[k * 4];
            a0[0] = fmaf(hv.x, w0, a0[0]); a1[0] = fmaf(hv.x, w1, a1[0]);
            a0[1] = fmaf(hv.y, w0, a0[1]); a1[1] = fmaf(hv.y, w1, a1[1]);
            a0[2] = fmaf(hv.z, w0, a0[2]); a1[2] = fmaf(hv.z, w1, a1[2]);
            a0[3] = fmaf(hv.w, w0, a0[3]); a1[3] = fmaf(hv.w, w1, a1[3]);
        }
        __syncwarp();
#pragma unroll
        for (int s = 0; s < 4; s++) {
            hw[lane * 4 + s] = fmaxf(a0[s], 0.f);
            hw[(lane + 32) * 4 + s] = fmaxf(a1[s], 0.f);
        }
        __syncwarp();

#pragma unroll
        for (int s = 0; s < 4; s++) { a0[s] = b3A; a1[s] = b3B; }
#pragma unroll 8
        for (int k = 0; k < 64; k++) {
            float w0 = sW3[k * 64 + lane], w1 = sW3[k * 64 + lane + 32];
            float4 hv = *(float4*)&hw[k * 4];
            a0[0] = fmaf(hv.x, w0, a0[0]); a1[0] = fmaf(hv.x, w1, a1[0]);
            a0[1] = fmaf(hv.y, w0, a0[1]); a1[1] = fmaf(hv.y, w1, a1[1]);
            a0[2] = fmaf(hv.z, w0, a0[2]); a1[2] = fmaf(hv.z, w1, a1[2]);
            a0[3] = fmaf(hv.w, w0, a0[3]); a1[3] = fmaf(hv.w, w1, a1[3]);
        }
#pragma unroll
        for (int s = 0; s < 4; s++) {
            if (base + s < 625) {
                gA += fmaxf(a0[s], 0.f);
                gB += fmaxf(a1[s], 0.f);
            }
        }
        __syncwarp();
    }
    sGp[warp * 64 + lane] = gA;
    sGp[warp * 64 + lane + 32] = gB;
    __syncthreads();
    if (tid < 64) {
        float s = 0.f;
#pragma unroll
        for (int w = 0; w < 8; w++) s += sGp[w * 64 + tid];
        gout[(size_t)b * 64 + tid] = s;
    }
}

__global__ void final_head_kernel(const float* __restrict__ lat,
                                  const float* __restrict__ Wf1, const float* __restrict__ bf1,
                                  const float* __restrict__ Wf2, const float* __restrict__ bf2,
                                  const float* __restrict__ Wf3, const float* __restrict__ bf3,
                                  float* __restrict__ out) {
    __shared__ float sh1[8][64];
    int tid = threadIdx.x, lane = tid & 31, warp = tid >> 5;
    int b = blockIdx.x * 8 + warp;
    float a0 = bf1[lane], a1 = bf1[lane + 32];
    const float* g0 = d_g0 + (size_t)b * 64;
    const float* g1 = d_g1 + (size_t)b * 64;
    const float* lr = lat + (size_t)b * 256;
    for (int k = 0; k < 64; k++) {
        float g = g0[k];
        a0 = fmaf(g, Wf1[k * 64 + lane], a0);
        a1 = fmaf(g, Wf1[k * 64 + lane + 32], a1);
    }
    for (int k = 0; k < 64; k++) {
        float g = g1[k];
        a0 = fmaf(g, Wf1[(64 + k) * 64 + lane], a0);
        a1 = fmaf(g, Wf1[(64 + k) * 64 + lane + 32], a1);
    }
    for (int k = 0; k < 256; k++) {
        float g = lr[k];
        a0 = fmaf(g, Wf1[(128 + k) * 64 + lane], a0);
        a1 = fmaf(g, Wf1[(128 + k) * 64 + lane + 32], a1);
    }
    sh1[warp][lane] = fmaxf(a0, 0.f);
    sh1[warp][lane + 32] = fmaxf(a1, 0.f);
    __syncwarp();
    float c = bf2[lane];
    for (int k = 0; k < 64; k++) c = fmaf(sh1[warp][k], Wf2[k * 32 + lane], c);
    c = fmaxf(c, 0.f);
    float v = c * Wf3[lane];
#pragma unroll
    for (int o = 16; o; o >>= 1) v += __shfl_down_sync(0xffffffffu, v, o);
    if (lane == 0) out[b] = v + bf3[0];
}

extern "C" void kernel_launch(void* const* d_in, const int* in_sizes, int n_in,
                              void* d_out, int out_size) {
    const float* x0 = (const float*)d_in[0];
    const float* x1 = (const float*)d_in[1];
    const float* lat = (const float*)d_in[2];
    const float* Wc1 = (const float*)d_in[3];
    const float* Wc2 = (const float*)d_in[4];
    const float* Wc3 = (const float*)d_in[5];
    const float* Wc4 = (const float*)d_in[6];
    const float* bng = (const float*)d_in[7];
    const float* bnb = (const float*)d_in[8];
    const float* Wg1 = (const float*)d_in[9];
    const float* bg1 = (const float*)d_in[10];
    const float* Wg2 = (const float*)d_in[11];
    const float* bg2 = (const float*)d_in[12];
    const float* Wg3 = (const float*)d_in[13];
    const float* bg3 = (const float*)d_in[14];
    const float* Wf1 = (const float*)d_in[15];
    const float* bf1 = (const float*)d_in[16];
    const float* Wf2 = (const float*)d_in[17];
    const float* bf2 = (const float*)d_in[18];
    const float* Wf3 = (const float*)d_in[19];
    const float* bf3 = (const float*)d_in[20];
    float* out = (float*)d_out;

    float *buf1, *buf2, *buf3, *buf4, *wt1, *statsA, *g0p, *g1p;
    uint4 *wf2, *wf3, *wf4;
    cudaGetSymbolAddress((void**)&buf1, d_buf1);
    cudaGetSymbolAddress((void**)&buf2, d_buf2);
    cudaGetSymbolAddress((void**)&buf3, d_buf3);
    cudaGetSymbolAddress((void**)&buf4, d_buf4);
    cudaGetSymbolAddress((void**)&wt1, d_Wt1);
    cudaGetSymbolAddress((void**)&wf2, d_Wf2);
    cudaGetSymbolAddress((void**)&wf3, d_Wf3);
    cudaGetSymbolAddress((void**)&wf4, d_Wf4);
    cudaGetSymbolAddress((void**)&statsA, d_statsA);
    cudaGetSymbolAddress((void**)&g0p, d_g0);
    cudaGetSymbolAddress((void**)&g1p, d_g1);

    const int REL_SMEM = 15668 * 4;
    cudaFuncSetAttribute(relation_kernel, cudaFuncAttributeMaxDynamicSharedMemorySize, REL_SMEM);
    const int MMA_SMEM = 2 * 2 * 32 * 136 * 4;   // 69632 B
    cudaFuncSetAttribute(conv_mma3_kernel<25, 25, 23, 23, 1>,
                         cudaFuncAttributeMaxDynamicSharedMemorySize, MMA_SMEM);
    cudaFuncSetAttribute(conv_mma3_kernel<23, 23, 11, 11, 2>,
                         cudaFuncAttributeMaxDynamicSharedMemorySize, MMA_SMEM);
    cudaFuncSetAttribute(conv_mma3_kernel<11, 11, 5, 5, 2>,
                         cudaFuncAttributeMaxDynamicSharedMemorySize, MMA_SMEM);

    zero_misc_kernel<<<1, 1024>>>();
    prep_weights_kernel<<<72, 256>>>(Wc1, Wc2, Wc3, Wc4);
    att_sum_kernel<<<64, 512>>>(lat);

    for (int im = 0; im < 2; im++) {
        const float* x = im ? x1 : x0;
        float* gp = im ? g1p : g0p;
        float* sl = statsA + im * 4 * 128;

        conv1_kernel<<<10000, 256>>>(x, wt1, buf1);
        stats_kernel<<<256, 256>>>(buf1, 640000, sl + 0 * 128);
        conv_mma3_kernel<25, 25, 23, 23, 1><<<4232, 256, MMA_SMEM>>>(
            buf1, wf2, buf2, sl + 0 * 128, bng + 0, bnb + 0, 1.f / 640000.f);
        stats_kernel<<<256, 256>>>(buf2, 541696, sl + 1 * 128);
        conv_mma3_kernel<23, 23, 11, 11, 2><<<968, 256, MMA_SMEM>>>(
            buf2, wf3, buf3, sl + 1 * 128, bng + 64, bnb + 64, 1.f / 541696.f);
        stats_kernel<<<256, 256>>>(buf3, 123904, sl + 2 * 128);
        conv_mma3_kernel<11, 11, 5, 5, 2><<<200, 256, MMA_SMEM>>>(
            buf3, wf4, buf4, sl + 2 * 128, bng + 128, bnb + 128, 1.f / 123904.f);
        stats_kernel<<<256, 256>>>(buf4, 25600, sl + 3 * 128);
        relation_kernel<<<1024, 256, REL_SMEM>>>(
            buf4, lat, Wg1, bg1, Wg2, bg2, Wg3, bg3,
            sl + 3 * 128, bng + 192, bnb + 192, 1.f / 25600.f, im, gp);
    }
    final_head_kernel<<<128, 256>>>(lat, Wf1, bf1, Wf2, bf2, Wf3, bf3, out);
}

// round 9
// speedup vs baseline: 1.8037x; 1.2501x over previous
#include <cuda_runtime.h>
#include <cuda_bf16.h>
#include <math.h>
#include <stdint.h>

// ---------------------------------------------------------------------------
// RelationNetworks forward. B=1024, C=64, L=64, H=64, IMG=27.
// conv chain: 27 ->(s1) 25 ->(s1) 23 ->(s2) 11 ->(s2) 5
// Activations NHWC [b][sp][c]. conv2/3/4 via mma.sync m16n8k16 bf16,
// 2-term (hi+lo) bf16 split, 4-pass product, fp32 accum.
// ---------------------------------------------------------------------------

__device__ float d_buf1[1024 * 625 * 64];
__device__ float d_buf2[1024 * 529 * 64];
__device__ float d_buf3[1024 * 121 * 64];
__device__ float d_buf4[1024 * 25 * 64];
__device__ float d_Wt1[32 * 64];          // conv1 [k pad32][oc]
// fragment-major packed bf16 weights:
// idx = (ch*2+wn)*256 + nf*64 + step*32 + lane -> {b0h, b1h, b0l, b1l}
__device__ uint4 d_Wf2[9216];
__device__ uint4 d_Wf3[9216];
__device__ uint4 d_Wf4[9216];
__device__ float d_statsA[8 * 128];
__device__ float d_Ssum[2];
__device__ float d_g0[1024 * 64];
__device__ float d_g1[1024 * 64];

// ---------------------------- helpers --------------------------------------
__device__ __forceinline__ uint16_t f2bf(float x, float& lo) {
    __nv_bfloat16 h = __float2bfloat16_rn(x);
    lo = x - __bfloat162float(h);
    return *(uint16_t*)&h;
}

__device__ __forceinline__ void mma_bf16(float c[4], const uint32_t a[4],
                                         uint32_t b0, uint32_t b1) {
    asm volatile(
        "mma.sync.aligned.m16n8k16.row.col.f32.bf16.bf16.f32 "
        "{%0,%1,%2,%3}, {%4,%5,%6,%7}, {%8,%9}, {%0,%1,%2,%3};"
        : "+f"(c[0]), "+f"(c[1]), "+f"(c[2]), "+f"(c[3])
        : "r"(a[0]), "r"(a[1]), "r"(a[2]), "r"(a[3]), "r"(b0), "r"(b1));
}

// ---------------------------- small kernels --------------------------------
__global__ void zero_misc_kernel() {
    int t = threadIdx.x;
    if (t < 1024) d_statsA[t] = 0.f;
    if (t < 2) d_Ssum[t] = 0.f;
}

// conv1 weight transpose + fragment-major bf16 hi/lo packing for conv2/3/4
__global__ void prep_weights_kernel(const float* __restrict__ Wc1,
                                    const float* __restrict__ Wc2,
                                    const float* __restrict__ Wc3,
                                    const float* __restrict__ Wc4) {
    int i = blockIdx.x * blockDim.x + threadIdx.x;
    if (i < 32 * 64) {
        int k = i >> 6, oc = i & 63;
        d_Wt1[i] = (k < 27) ? Wc1[oc * 27 + (k % 3) * 9 + (k / 3)] : 0.f;
    }
    if (i < 9216) {
        int lane = i & 31;
        int step = (i >> 5) & 1;
        int nf = (i >> 6) & 3;
        int wn = (i >> 8) & 1;
        int ch = i >> 9;                       // 0..17
        int n = wn * 32 + nf * 8 + (lane >> 2);
        int lt = lane & 3;
        int kb = ch * 32 + step * 16;
        int ks[4] = {kb + 2 * lt, kb + 2 * lt + 1, kb + 2 * lt + 8, kb + 2 * lt + 9};
        const float* Ws[3] = {Wc2, Wc3, Wc4};
        uint4* Wd[3] = {d_Wf2, d_Wf3, d_Wf4};
#pragma unroll
        for (int L = 0; L < 3; L++) {
            uint16_t h[4];
            float lo[4];
#pragma unroll
            for (int e = 0; e < 4; e++) {
                int k = ks[e];
                float v = Ws[L][n * 576 + (k & 63) * 9 + (k >> 6)];
                h[e] = f2bf(v, lo[e]);
            }
            uint16_t l0 = f2bf(lo[0], lo[0]), l1 = f2bf(lo[1], lo[1]);
            uint16_t l2 = f2bf(lo[2], lo[2]), l3 = f2bf(lo[3], lo[3]);
            Wd[L][i] = make_uint4(((uint32_t)h[1] << 16) | h[0],
                                  ((uint32_t)h[3] << 16) | h[2],
                                  ((uint32_t)l1 << 16) | l0,
                                  ((uint32_t)l3 << 16) | l2);
        }
    }
}

__global__ void att_sum_kernel(const float* __restrict__ lat) {
    int i = blockIdx.x * blockDim.x + threadIdx.x;
    float p0 = 0.f, p1 = 0.f;
    for (int idx = i; idx < 65536; idx += gridDim.x * blockDim.x) {
        int b = idx >> 6, c = idx & 63;
        p0 += expf(lat[(b * 4 + 2) * 64 + c]);
        p1 += expf(lat[(b * 4 + 3) * 64 + c]);
    }
#pragma unroll
    for (int o = 16; o; o >>= 1) {
        p0 += __shfl_down_sync(0xffffffffu, p0, o);
        p1 += __shfl_down_sync(0xffffffffu, p1, o);
    }
    if ((threadIdx.x & 31) == 0) {
        atomicAdd(&d_Ssum[0], p0);
        atomicAdd(&d_Ssum[1], p1);
    }
}

__global__ void __launch_bounds__(256) stats_kernel(
    const float* __restrict__ buf, int rows, float* __restrict__ slot) {
    __shared__ float red[2][64][16];
    int tid = threadIdx.x;
    int c4 = tid & 15, j = tid >> 4;
    float4 s = make_float4(0.f, 0.f, 0.f, 0.f);
    float4 q = make_float4(0.f, 0.f, 0.f, 0.f);
    for (int r = blockIdx.x * 16 + j; r < rows; r += gridDim.x * 16) {
        float4 v = *(const float4*)(buf + (size_t)r * 64 + c4 * 4);
        s.x += v.x; s.y += v.y; s.z += v.z; s.w += v.w;
        q.x += v.x * v.x; q.y += v.y * v.y; q.z += v.z * v.z; q.w += v.w * v.w;
    }
    red[0][c4 * 4 + 0][j] = s.x; red[0][c4 * 4 + 1][j] = s.y;
    red[0][c4 * 4 + 2][j] = s.z; red[0][c4 * 4 + 3][j] = s.w;
    red[1][c4 * 4 + 0][j] = q.x; red[1][c4 * 4 + 1][j] = q.y;
    red[1][c4 * 4 + 2][j] = q.z; red[1][c4 * 4 + 3][j] = q.w;
    __syncthreads();
    if (tid < 128) {
        int si = tid >> 6, c = tid & 63;
        float v = 0.f;
#pragma unroll
        for (int t = 0; t < 16; t++) v += red[si][c][t];
        atomicAdd(&slot[si * 64 + c], v);
    }
}

// ---- conv1: NCHW input (3 ch), NHWC raw output. SIMT GEMM ----------------
__global__ void __launch_bounds__(256) conv1_kernel(
    const float* __restrict__ in, const float* __restrict__ Wt,
    float* __restrict__ out) {
    constexpr int BK = 16;
    __shared__ float As[BK][64];
    __shared__ float Bs[BK][64];

    const int tid = threadIdx.x;
    const int tx = tid & 15, ty = tid >> 4;
    const int m0 = blockIdx.x * 64;

    const int mi = tid >> 2;
    const int kb = (tid & 3) * 4;
    const int mg = m0 + mi;
    const int bI = mg / 625;
    const int sp = mg - bI * 625;
    const int oy = sp / 25;
    const int ox = sp - oy * 25;
    const float* inb = in + ((size_t)bI * 3) * 729 + oy * 27 + ox;

    float acc[4][4];
#pragma unroll
    for (int i = 0; i < 4; i++)
#pragma unroll
        for (int j = 0; j < 4; j++) acc[i][j] = 0.f;

    for (int k0 = 0; k0 < 32; k0 += BK) {
        {
            int ki = tid >> 4;
            int oc = (tid & 15) * 4;
            *(float4*)&Bs[ki][oc] = *(const float4*)(Wt + (k0 + ki) * 64 + oc);
        }
#pragma unroll
        for (int j = 0; j < 4; j++) {
            int k = k0 + kb + j;
            float v = 0.f;
            if (k < 27) {
                int w = k / 3, ic = k - w * 3;
                int ky = w / 3, kx = w - ky * 3;
                v = inb[ic * 729 + ky * 27 + kx];
            }
            As[kb + j][mi] = v;
        }
        __syncthreads();
#pragma unroll
        for (int kk = 0; kk < BK; kk++) {
            float4 a4 = *(float4*)&As[kk][ty * 4];
            float4 b4 = *(float4*)&Bs[kk][tx * 4];
            float av[4] = {a4.x, a4.y, a4.z, a4.w};
            float bw[4] = {b4.x, b4.y, b4.z, b4.w};
#pragma unroll
            for (int i = 0; i < 4; i++)
#pragma unroll
                for (int j = 0; j < 4; j++)
                    acc[i][j] = fmaf(av[i], bw[j], acc[i][j]);
        }
        __syncthreads();
    }
#pragma unroll
    for (int i = 0; i < 4; i++) {
        float4 v = make_float4(acc[i][0], acc[i][1], acc[i][2], acc[i][3]);
        *(float4*)(out + (size_t)(m0 + ty * 4 + i) * 64 + tx * 4) = v;
    }
}

// ---- conv64 via mma.sync bf16 hi/lo: BM=128, BN=64, BK=32, double-buffer --
// A smem as bf16x2 [k2 16][row pad136] per stage (hi then lo).
template <int IH, int IW, int OH, int OW, int STRIDE>
__global__ void __launch_bounds__(256) conv_mma3_kernel(
    const float* __restrict__ in, const uint4* __restrict__ Wf,
    float* __restrict__ out,
    const float* __restrict__ stats, const float* __restrict__ bn_g,
    const float* __restrict__ bn_b, float invN) {
    constexpr int OSP = OH * OW;
    constexpr int STG = 4352;                 // u32 per stage (hi 2176 + lo 2176)
    extern __shared__ uint32_t smu[];
    __shared__ float sBn[128];

    const int tid = threadIdx.x;
    const int lane = tid & 31, warp = tid >> 5;
    const int wm = warp & 3, wn = warp >> 2;
    const int lg = lane >> 2, lt = lane & 3;

    if (tid < 64) {
        float s = stats[tid], q = stats[64 + tid];
        float mean = s * invN;
        float var = q * invN - mean * mean;
        float sc = bn_g[tid] * rsqrtf(var + 1e-5f);
        sBn[tid] = sc;
        sBn[64 + tid] = bn_b[tid] - mean * sc;
    }

    // producer coords: one row per 2 threads, 16 k each
    const int row = tid >> 1;
    const int khalf = tid & 1;
    const int mg = blockIdx.x * 128 + row;
    const int bI = mg / OSP;
    const int sp = mg - bI * OSP;
    const int oy = sp / OW;
    const int ox = sp - oy * OW;
    const float* inb = in + (((size_t)bI * IH + oy * STRIDE) * IW + ox * STRIDE) * 64;

    float c[2][4][4];
#pragma unroll
    for (int m = 0; m < 2; m++)
#pragma unroll
        for (int n = 0; n < 4; n++)
#pragma unroll
            for (int e = 0; e < 4; e++) c[m][n][e] = 0.f;

    __syncthreads();

    // fill chunk ch into stage s: BN+ReLU, bf16 hi/lo split, pack k-pairs
    auto fill = [&](int s, int ch) {
        const int w = ch >> 1;
        const int ic0 = (ch & 1) * 32;
        const int ky = w / 3, kx = w - ky * 3;
        uint32_t* aH = smu + s * STG;
        uint32_t* aL = aH + 2176;
        const float* src = inb + (ky * IW + kx) * 64 + ic0 + khalf * 16;
        float xs[16];
#pragma unroll
        for (int j = 0; j < 4; j++) {
            float4 v = *(const float4*)(src + j * 4);
            int icb = ic0 + khalf * 16 + j * 4;
            float4 sc = *(const float4*)&sBn[icb];
            float4 sh = *(const float4*)&sBn[64 + icb];
            xs[j * 4 + 0] = fmaxf(fmaf(v.x, sc.x, sh.x), 0.f);
            xs[j * 4 + 1] = fmaxf(fmaf(v.y, sc.y, sh.y), 0.f);
            xs[j * 4 + 2] = fmaxf(fmaf(v.z, sc.z, sh.z), 0.f);
            xs[j * 4 + 3] = fmaxf(fmaf(v.w, sc.w, sh.w), 0.f);
        }
#pragma unroll
        for (int jj = 0; jj < 8; jj++) {
            float r0, r1;
            uint16_t h0 = f2bf(xs[2 * jj], r0);
            uint16_t h1 = f2bf(xs[2 * jj + 1], r1);
            uint16_t l0 = f2bf(r0, r0);
            uint16_t l1 = f2bf(r1, r1);
            int k2g = khalf * 8 + jj;
            aH[k2g * 136 + row] = ((uint32_t)h1 << 16) | h0;
            aL[k2g * 136 + row] = ((uint32_t)l1 << 16) | l0;
        }
    };

    fill(0, 0);
    __syncthreads();

#pragma unroll 1
    for (int ch = 0; ch < 18; ch++) {
        if (ch + 1 < 18) fill((ch + 1) & 1, ch + 1);

        const uint32_t* aH = smu + (ch & 1) * STG;
        const uint32_t* aL = aH + 2176;
        const uint4* wp = Wf + (size_t)(ch * 2 + wn) * 256 + lane;
#pragma unroll
        for (int step = 0; step < 2; step++) {
            uint32_t ah[2][4], al[2][4];
#pragma unroll
            for (int m = 0; m < 2; m++) {
                int rf = wm * 32 + m * 16 + lg;
                int k2 = step * 8 + lt;
                ah[m][0] = aH[k2 * 136 + rf];
                ah[m][1] = aH[k2 * 136 + rf + 8];
                ah[m][2] = aH[(k2 + 4) * 136 + rf];
                ah[m][3] = aH[(k2 + 4) * 136 + rf + 8];
                al[m][0] = aL[k2 * 136 + rf];
                al[m][1] = aL[k2 * 136 + rf + 8];
                al[m][2] = aL[(k2 + 4) * 136 + rf];
                al[m][3] = aL[(k2 + 4) * 136 + rf + 8];
            }
#pragma unroll
            for (int nf = 0; nf < 4; nf++) {
                uint4 b = wp[nf * 64 + step * 32];
#pragma unroll
                for (int m = 0; m < 2; m++) {
                    mma_bf16(c[m][nf], ah[m], b.x, b.y);   // hi*hi
                    mma_bf16(c[m][nf], ah[m], b.z, b.w);   // hi*lo
                    mma_bf16(c[m][nf], al[m], b.x, b.y);   // lo*hi
                    mma_bf16(c[m][nf], al[m], b.z, b.w);   // lo*lo
                }
            }
        }
        __syncthreads();
    }

    // epilogue: raw NHWC stores (C-fragment mapping validated in rounds 6/8)
#pragma unroll
    for (int m = 0; m < 2; m++) {
        int r = blockIdx.x * 128 + wm * 32 + m * 16 + lg;
#pragma unroll
        for (int nf = 0; nf < 4; nf++) {
            int col = wn * 32 + nf * 8 + lt * 2;
            *(float2*)(out + (size_t)r * 64 + col) =
                make_float2(c[m][nf][0], c[m][nf][1]);
            *(float2*)(out + (size_t)(r + 8) * 64 + col) =
                make_float2(c[m][nf][2], c[m][nf][3]);
        }
    }
}

// ---- relation network: one block per batch element ------------------------
__global__ void __launch_bounds__(256) relation_kernel(
    const float* __restrict__ conv4, const float* __restrict__ lat,
    const float* __restrict__ Wg1, const float* __restrict__ bg1,
    const float* __restrict__ Wg2, const float* __restrict__ bg2,
    const float* __restrict__ Wg3, const float* __restrict__ bg3,
    const float* __restrict__ stats, const float* __restrict__ bn_g,
    const float* __restrict__ bn_b, float invN,
    int im, float* __restrict__ gout) {
    extern __shared__ float sm[];
    float* sW2 = sm;
    float* sW3 = sm + 4096;
    float* sTi = sm + 8192;
    float* sTj = sm + 9792;
    float* sCT = sm + 11392;
    float* sTw = sm + 13042;
    float* sH  = sm + 13108;
    float* sGp = sm + 15156;
    __shared__ float sBn[128];

    const int tid = threadIdx.x;
    const int b = blockIdx.x;
    const int lane = tid & 31, warp = tid >> 5;

    if (tid < 64) {
        float s = stats[tid], q = stats[64 + tid];
        float mean = s * invN;
        float var = q * invN - mean * mean;
        float sc = bn_g[tid] * rsqrtf(var + 1e-5f);
        sBn[tid] = sc;
        sBn[64 + tid] = bn_b[tid] - mean * sc;
    }
    for (int i = tid; i < 4096; i += 256) {
        sW2[i] = Wg2[i];
        sW3[i] = Wg3[i];
    }
    __syncthreads();

    const float invS = 1.f / (d_Ssum[im] + 1e-9f);
    const float* aRow = lat + ((size_t)b * 4 + 2 + im) * 64;
    const float* wRow = lat + ((size_t)b * 4 + im) * 64;

    for (int i = tid; i < 1600; i += 256) {
        int p = i >> 6, cc = i & 63;
        float v = conv4[((size_t)b * 25 + p) * 64 + cc];
        v = fmaxf(fmaf(v, sBn[cc], sBn[64 + cc]), 0.f);
        v *= expf(aRow[cc]) * invS;
        sCT[p * 66 + cc] = v;
    }
    if (tid < 50) {
        int p = tid % 25, cc = tid / 25;
        sCT[p * 66 + 64 + cc] = (cc == 0) ? (float)(p % 5) - 2.f : (float)(p / 5) - 2.f;
    }
    if (tid < 64) {
        float acc = bg1[tid];
        for (int cc = 0; cc < 64; cc++)
            acc = fmaf(wRow[cc], Wg1[(132 + cc) * 64 + tid], acc);
        sTw[tid] = acc;
    }
    __syncthreads();

    for (int o = tid; o < 1600; o += 256) {
        int p = o >> 6, h = o & 63;
        float aj = 0.f, ai = 0.f;
        for (int cc = 0; cc < 66; cc++) {
            float ctv = sCT[p * 66 + cc];
            aj = fmaf(ctv, Wg1[cc * 64 + h], aj);
            ai = fmaf(ctv, Wg1[(66 + cc) * 64 + h], ai);
        }
        sTj[p * 64 + h] = aj;
        sTi[p * 64 + h] = ai;
    }
    __syncthreads();

    const float twA = sTw[lane], twB = sTw[lane + 32];
    const float b2A = bg2[lane], b2B = bg2[lane + 32];
    const float b3A = bg3[lane], b3B = bg3[lane + 32];
    float gA = 0.f, gB = 0.f;
    float* hw = sH + warp * 256;

    for (int it = 0; it < 20; it++) {
        const int base = it * 32 + warp * 4;
#pragma unroll
        for (int s = 0; s < 4; s++) {
            int pr = base + s;
            bool vld = pr < 625;
            int p = vld ? pr / 25 : 0, qq = vld ? pr % 25 : 0;
            hw[lane * 4 + s] = fmaxf(sTi[p * 64 + lane] + sTj[qq * 64 + lane] + twA, 0.f);
            hw[(lane + 32) * 4 + s] =
                fmaxf(sTi[p * 64 + lane + 32] + sTj[qq * 64 + lane + 32] + twB, 0.f);
        }
        __syncwarp();

        float a0[4], a1[4];
#pragma unroll
        for (int s = 0; s < 4; s++) { a0[s] = b2A; a1[s] = b2B; }
#pragma unroll 8
        for (int k = 0; k < 64; k++) {
            float w0 = sW2[k * 64 + lane], w1 = sW2[k * 64 + lane + 32];
            float4 hv = *(float4*)&hw[k * 4];
            a0[0] = fmaf(hv.x, w0, a0[0]); a1[0] = fmaf(hv.x, w1, a1[0]);
            a0[1] = fmaf(hv.y, w0, a0[1]); a1[1] = fmaf(hv.y, w1, a1[1]);
            a0[2] = fmaf(hv.z, w0, a0[2]); a1[2] = fmaf(hv.z, w1, a1[2]);
            a0[3] = fmaf(hv.w, w0, a0[3]); a1[3] = fmaf(hv.w, w1, a1[3]);
        }
        __syncwarp();
#pragma unroll
        for (int s = 0; s < 4; s++) {
            hw[lane * 4 + s] = fmaxf(a0[s], 0.f);
            hw[(lane + 32) * 4 + s] = fmaxf(a1[s], 0.f);
        }
        __syncwarp();

#pragma unroll
        for (int s = 0; s < 4; s++) { a0[s] = b3A; a1[s] = b3B; }
#pragma unroll 8
        for (int k = 0; k < 64; k++) {
            float w0 = sW3[k * 64 + lane], w1 = sW3[k * 64 + lane + 32];
            float4 hv = *(float4*)&hw[k * 4];
            a0[0] = fmaf(hv.x, w0, a0[0]); a1[0] = fmaf(hv.x, w1, a1[0]);
            a0[1] = fmaf(hv.y, w0, a0[1]); a1[1] = fmaf(hv.y, w1, a1[1]);
            a0[2] = fmaf(hv.z, w0, a0[2]); a1[2] = fmaf(hv.z, w1, a1[2]);
            a0[3] = fmaf(hv.w, w0, a0[3]); a1[3] = fmaf(hv.w, w1, a1[3]);
        }
#pragma unroll
        for (int s = 0; s < 4; s++) {
            if (base + s < 625) {
                gA += fmaxf(a0[s], 0.f);
                gB += fmaxf(a1[s], 0.f);
            }
        }
        __syncwarp();
    }
    sGp[warp * 64 + lane] = gA;
    sGp[warp * 64 + lane + 32] = gB;
    __syncthreads();
    if (tid < 64) {
        float s = 0.f;
#pragma unroll
        for (int w = 0; w < 8; w++) s += sGp[w * 64 + tid];
        gout[(size_t)b * 64 + tid] = s;
    }
}

__global__ void final_head_kernel(const float* __restrict__ lat,
                                  const float* __restrict__ Wf1, const float* __restrict__ bf1,
                                  const float* __restrict__ Wf2, const float* __restrict__ bf2,
                                  const float* __restrict__ Wf3, const float* __restrict__ bf3,
                                  float* __restrict__ out) {
    __shared__ float sh1[8][64];
    int tid = threadIdx.x, lane = tid & 31, warp = tid >> 5;
    int b = blockIdx.x * 8 + warp;
    float a0 = bf1[lane], a1 = bf1[lane + 32];
    const float* g0 = d_g0 + (size_t)b * 64;
    const float* g1 = d_g1 + (size_t)b * 64;
    const float* lr = lat + (size_t)b * 256;
    for (int k = 0; k < 64; k++) {
        float g = g0[k];
        a0 = fmaf(g, Wf1[k * 64 + lane], a0);
        a1 = fmaf(g, Wf1[k * 64 + lane + 32], a1);
    }
    for (int k = 0; k < 64; k++) {
        float g = g1[k];
        a0 = fmaf(g, Wf1[(64 + k) * 64 + lane], a0);
        a1 = fmaf(g, Wf1[(64 + k) * 64 + lane + 32], a1);
    }
    for (int k = 0; k < 256; k++) {
        float g = lr[k];
        a0 = fmaf(g, Wf1[(128 + k) * 64 + lane], a0);
        a1 = fmaf(g, Wf1[(128 + k) * 64 + lane + 32], a1);
    }
    sh1[warp][lane] = fmaxf(a0, 0.f);
    sh1[warp][lane + 32] = fmaxf(a1, 0.f);
    __syncwarp();
    float c = bf2[lane];
    for (int k = 0; k < 64; k++) c = fmaf(sh1[warp][k], Wf2[k * 32 + lane], c);
    c = fmaxf(c, 0.f);
    float v = c * Wf3[lane];
#pragma unroll
    for (int o = 16; o; o >>= 1) v += __shfl_down_sync(0xffffffffu, v, o);
    if (lane == 0) out[b] = v + bf3[0];
}

extern "C" void kernel_launch(void* const* d_in, const int* in_sizes, int n_in,
                              void* d_out, int out_size) {
    const float* x0 = (const float*)d_in[0];
    const float* x1 = (const float*)d_in[1];
    const float* lat = (const float*)d_in[2];
    const float* Wc1 = (const float*)d_in[3];
    const float* Wc2 = (const float*)d_in[4];
    const float* Wc3 = (const float*)d_in[5];
    const float* Wc4 = (const float*)d_in[6];
    const float* bng = (const float*)d_in[7];
    const float* bnb = (const float*)d_in[8];
    const float* Wg1 = (const float*)d_in[9];
    const float* bg1 = (const float*)d_in[10];
    const float* Wg2 = (const float*)d_in[11];
    const float* bg2 = (const float*)d_in[12];
    const float* Wg3 = (const float*)d_in[13];
    const float* bg3 = (const float*)d_in[14];
    const float* Wf1 = (const float*)d_in[15];
    const float* bf1 = (const float*)d_in[16];
    const float* Wf2 = (const float*)d_in[17];
    const float* bf2 = (const float*)d_in[18];
    const float* Wf3 = (const float*)d_in[19];
    const float* bf3 = (const float*)d_in[20];
    float* out = (float*)d_out;

    float *buf1, *buf2, *buf3, *buf4, *wt1, *statsA, *g0p, *g1p;
    uint4 *wf2, *wf3, *wf4;
    cudaGetSymbolAddress((void**)&buf1, d_buf1);
    cudaGetSymbolAddress((void**)&buf2, d_buf2);
    cudaGetSymbolAddress((void**)&buf3, d_buf3);
    cudaGetSymbolAddress((void**)&buf4, d_buf4);
    cudaGetSymbolAddress((void**)&wt1, d_Wt1);
    cudaGetSymbolAddress((void**)&wf2, d_Wf2);
    cudaGetSymbolAddress((void**)&wf3, d_Wf3);
    cudaGetSymbolAddress((void**)&wf4, d_Wf4);
    cudaGetSymbolAddress((void**)&statsA, d_statsA);
    cudaGetSymbolAddress((void**)&g0p, d_g0);
    cudaGetSymbolAddress((void**)&g1p, d_g1);

    const int REL_SMEM = 15668 * 4;
    cudaFuncSetAttribute(relation_kernel, cudaFuncAttributeMaxDynamicSharedMemorySize, REL_SMEM);
    const int MMA_SMEM = 2 * 4352 * 4;   // 34816 B
    cudaFuncSetAttribute(conv_mma3_kernel<25, 25, 23, 23, 1>,
                         cudaFuncAttributeMaxDynamicSharedMemorySize, MMA_SMEM);
    cudaFuncSetAttribute(conv_mma3_kernel<23, 23, 11, 11, 2>,
                         cudaFuncAttributeMaxDynamicSharedMemorySize, MMA_SMEM);
    cudaFuncSetAttribute(conv_mma3_kernel<11, 11, 5, 5, 2>,
                         cudaFuncAttributeMaxDynamicSharedMemorySize, MMA_SMEM);

    zero_misc_kernel<<<1, 1024>>>();
    prep_weights_kernel<<<36, 256>>>(Wc1, Wc2, Wc3, Wc4);
    att_sum_kernel<<<64, 512>>>(lat);

    for (int im = 0; im < 2; im++) {
        const float* x = im ? x1 : x0;
        float* gp = im ? g1p : g0p;
        float* sl = statsA + im * 4 * 128;

        conv1_kernel<<<10000, 256>>>(x, wt1, buf1);
        stats_kernel<<<256, 256>>>(buf1, 640000, sl + 0 * 128);
        conv_mma3_kernel<25, 25, 23, 23, 1><<<4232, 256, MMA_SMEM>>>(
            buf1, wf2, buf2, sl + 0 * 128, bng + 0, bnb + 0, 1.f / 640000.f);
        stats_kernel<<<256, 256>>>(buf2, 541696, sl + 1 * 128);
        conv_mma3_kernel<23, 23, 11, 11, 2><<<968, 256, MMA_SMEM>>>(
            buf2, wf3, buf3, sl + 1 * 128, bng + 64, bnb + 64, 1.f / 541696.f);
        stats_kernel<<<256, 256>>>(buf3, 123904, sl + 2 * 128);
        conv_mma3_kernel<11, 11, 5, 5, 2><<<200, 256, MMA_SMEM>>>(
            buf3, wf4, buf4, sl + 2 * 128, bng + 128, bnb + 128, 1.f / 123904.f);
        stats_kernel<<<256, 256>>>(buf4, 25600, sl + 3 * 128);
        relation_kernel<<<1024, 256, REL_SMEM>>>(
            buf4, lat, Wg1, bg1, Wg2, bg2, Wg3, bg3,
            sl + 3 * 128, bng + 192, bnb + 192, 1.f / 25600.f, im, gp);
    }
    final_head_kernel<<<128, 256>>>(lat, Wf1, bf1, Wf2, bf2, Wf3, bf3, out);
}

// round 10
// speedup vs baseline: 2.1424x; 1.1878x over previous
#include <cuda_runtime.h>
#include <cuda_bf16.h>
#include <math.h>
#include <stdint.h>

// ---------------------------------------------------------------------------
// RelationNetworks forward. B=1024, C=64, L=64, H=64, IMG=27.
// conv chain: 27 ->(s1) 25 ->(s1) 23 ->(s2) 11 ->(s2) 5
// Activations NHWC [b][sp][c]. conv2/3/4 via mma.sync m16n8k16 bf16,
// 2-term (hi+lo) split, 3-pass product (hh+hl+lh), fp32 accum.
// BN stats fused into conv epilogues.
// ---------------------------------------------------------------------------

__device__ float d_buf1[1024 * 625 * 64];
__device__ float d_buf2[1024 * 529 * 64];
__device__ float d_buf3[1024 * 121 * 64];
__device__ float d_buf4[1024 * 25 * 64];
__device__ float d_Wt1[32 * 64];          // conv1 [k pad32][oc]
// fragment-major packed bf16 weights:
// idx = (ch*2+wn)*256 + nf*64 + step*32 + lane -> {b0h, b1h, b0l, b1l}
__device__ uint4 d_Wf2[9216];
__device__ uint4 d_Wf3[9216];
__device__ uint4 d_Wf4[9216];
__device__ float d_statsA[8 * 128];
__device__ float d_Ssum[2];
__device__ float d_g0[1024 * 64];
__device__ float d_g1[1024 * 64];

// ---------------------------- helpers --------------------------------------
__device__ __forceinline__ uint16_t f2bf(float x, float& lo) {
    __nv_bfloat16 h = __float2bfloat16_rn(x);
    lo = x - __bfloat162float(h);
    return *(uint16_t*)&h;
}

__device__ __forceinline__ void mma_bf16(float c[4], const uint32_t a[4],
                                         uint32_t b0, uint32_t b1) {
    asm volatile(
        "mma.sync.aligned.m16n8k16.row.col.f32.bf16.bf16.f32 "
        "{%0,%1,%2,%3}, {%4,%5,%6,%7}, {%8,%9}, {%0,%1,%2,%3};"
        : "+f"(c[0]), "+f"(c[1]), "+f"(c[2]), "+f"(c[3])
        : "r"(a[0]), "r"(a[1]), "r"(a[2]), "r"(a[3]), "r"(b0), "r"(b1));
}

// ---------------------------- small kernels --------------------------------
__global__ void zero_misc_kernel() {
    int t = threadIdx.x;
    if (t < 1024) d_statsA[t] = 0.f;
    if (t < 2) d_Ssum[t] = 0.f;
}

__global__ void prep_weights_kernel(const float* __restrict__ Wc1,
                                    const float* __restrict__ Wc2,
                                    const float* __restrict__ Wc3,
                                    const float* __restrict__ Wc4) {
    int i = blockIdx.x * blockDim.x + threadIdx.x;
    if (i < 32 * 64) {
        int k = i >> 6, oc = i & 63;
        d_Wt1[i] = (k < 27) ? Wc1[oc * 27 + (k % 3) * 9 + (k / 3)] : 0.f;
    }
    if (i < 9216) {
        int lane = i & 31;
        int step = (i >> 5) & 1;
        int nf = (i >> 6) & 3;
        int wn = (i >> 8) & 1;
        int ch = i >> 9;                       // 0..17
        int n = wn * 32 + nf * 8 + (lane >> 2);
        int lt = lane & 3;
        int kb = ch * 32 + step * 16;
        int ks[4] = {kb + 2 * lt, kb + 2 * lt + 1, kb + 2 * lt + 8, kb + 2 * lt + 9};
        const float* Ws[3] = {Wc2, Wc3, Wc4};
        uint4* Wd[3] = {d_Wf2, d_Wf3, d_Wf4};
#pragma unroll
        for (int L = 0; L < 3; L++) {
            uint16_t h[4];
            float lo[4];
#pragma unroll
            for (int e = 0; e < 4; e++) {
                int k = ks[e];
                float v = Ws[L][n * 576 + (k & 63) * 9 + (k >> 6)];
                h[e] = f2bf(v, lo[e]);
            }
            uint16_t l0 = f2bf(lo[0], lo[0]), l1 = f2bf(lo[1], lo[1]);
            uint16_t l2 = f2bf(lo[2], lo[2]), l3 = f2bf(lo[3], lo[3]);
            Wd[L][i] = make_uint4(((uint32_t)h[1] << 16) | h[0],
                                  ((uint32_t)h[3] << 16) | h[2],
                                  ((uint32_t)l1 << 16) | l0,
                                  ((uint32_t)l3 << 16) | l2);
        }
    }
}

__global__ void att_sum_kernel(const float* __restrict__ lat) {
    int i = blockIdx.x * blockDim.x + threadIdx.x;
    float p0 = 0.f, p1 = 0.f;
    for (int idx = i; idx < 65536; idx += gridDim.x * blockDim.x) {
        int b = idx >> 6, c = idx & 63;
        p0 += expf(lat[(b * 4 + 2) * 64 + c]);
        p1 += expf(lat[(b * 4 + 3) * 64 + c]);
    }
#pragma unroll
    for (int o = 16; o; o >>= 1) {
        p0 += __shfl_down_sync(0xffffffffu, p0, o);
        p1 += __shfl_down_sync(0xffffffffu, p1, o);
    }
    if ((threadIdx.x & 31) == 0) {
        atomicAdd(&d_Ssum[0], p0);
        atomicAdd(&d_Ssum[1], p1);
    }
}

// ---- conv1: NCHW input (3 ch), NHWC raw output + fused stats --------------
__global__ void __launch_bounds__(256) conv1_kernel(
    const float* __restrict__ in, const float* __restrict__ Wt,
    float* __restrict__ out, float* __restrict__ slot) {
    constexpr int BK = 16;
    __shared__ float As[BK][64];
    __shared__ float Bs[BK][64];
    __shared__ float red[2][64][16];

    const int tid = threadIdx.x;
    const int tx = tid & 15, ty = tid >> 4;
    const int m0 = blockIdx.x * 64;

    const int mi = tid >> 2;
    const int kb = (tid & 3) * 4;
    const int mg = m0 + mi;
    const int bI = mg / 625;
    const int sp = mg - bI * 625;
    const int oy = sp / 25;
    const int ox = sp - oy * 25;
    const float* inb = in + ((size_t)bI * 3) * 729 + oy * 27 + ox;

    float acc[4][4];
#pragma unroll
    for (int i = 0; i < 4; i++)
#pragma unroll
        for (int j = 0; j < 4; j++) acc[i][j] = 0.f;

    for (int k0 = 0; k0 < 32; k0 += BK) {
        {
            int ki = tid >> 4;
            int oc = (tid & 15) * 4;
            *(float4*)&Bs[ki][oc] = *(const float4*)(Wt + (k0 + ki) * 64 + oc);
        }
#pragma unroll
        for (int j = 0; j < 4; j++) {
            int k = k0 + kb + j;
            float v = 0.f;
            if (k < 27) {
                int w = k / 3, ic = k - w * 3;
                int ky = w / 3, kx = w - ky * 3;
                v = inb[ic * 729 + ky * 27 + kx];
            }
            As[kb + j][mi] = v;
        }
        __syncthreads();
#pragma unroll
        for (int kk = 0; kk < BK; kk++) {
            float4 a4 = *(float4*)&As[kk][ty * 4];
            float4 b4 = *(float4*)&Bs[kk][tx * 4];
            float av[4] = {a4.x, a4.y, a4.z, a4.w};
            float bw[4] = {b4.x, b4.y, b4.z, b4.w};
#pragma unroll
            for (int i = 0; i < 4; i++)
#pragma unroll
                for (int j = 0; j < 4; j++)
                    acc[i][j] = fmaf(av[i], bw[j], acc[i][j]);
        }
        __syncthreads();
    }
#pragma unroll
    for (int j = 0; j < 4; j++) {
        float s = 0.f, q = 0.f;
#pragma unroll
        for (int i = 0; i < 4; i++) {
            float v = acc[i][j];
            s += v;
            q += v * v;
        }
        red[0][tx * 4 + j][ty] = s;
        red[1][tx * 4 + j][ty] = q;
    }
#pragma unroll
    for (int i = 0; i < 4; i++) {
        float4 v = make_float4(acc[i][0], acc[i][1], acc[i][2], acc[i][3]);
        *(float4*)(out + (size_t)(m0 + ty * 4 + i) * 64 + tx * 4) = v;
    }
    __syncthreads();
    if (tid < 128) {
        int s = tid >> 6, c = tid & 63;
        float v = 0.f;
#pragma unroll
        for (int t = 0; t < 16; t++) v += red[s][c][t];
        atomicAdd(&slot[s * 64 + c], v);
    }
}

// ---- conv64 via mma.sync bf16 hi/lo (3-pass): BM=128, BN=64, BK=32 --------
// A smem as bf16x2 [k2 16][row pad136] per stage (hi then lo). Fused stats.
template <int IH, int IW, int OH, int OW, int STRIDE>
__global__ void __launch_bounds__(256) conv_mma3_kernel(
    const float* __restrict__ in, const uint4* __restrict__ Wf,
    float* __restrict__ out,
    const float* __restrict__ stats, const float* __restrict__ bn_g,
    const float* __restrict__ bn_b, float invN, float* __restrict__ slot) {
    constexpr int OSP = OH * OW;
    constexpr int STG = 4352;                 // u32 per stage (hi 2176 + lo 2176)
    extern __shared__ uint32_t smu[];
    __shared__ float sBn[128];
    __shared__ float sred[2][64][8];

    const int tid = threadIdx.x;
    const int lane = tid & 31, warp = tid >> 5;
    const int wm = warp & 3, wn = warp >> 2;
    const int lg = lane >> 2, lt = lane & 3;

    if (tid < 64) {
        float s = stats[tid], q = stats[64 + tid];
        float mean = s * invN;
        float var = q * invN - mean * mean;
        float sc = bn_g[tid] * rsqrtf(var + 1e-5f);
        sBn[tid] = sc;
        sBn[64 + tid] = bn_b[tid] - mean * sc;
    }

    // producer coords: one row per 2 threads, 16 k each
    const int row = tid >> 1;
    const int khalf = tid & 1;
    const int mg = blockIdx.x * 128 + row;
    const int bI = mg / OSP;
    const int sp = mg - bI * OSP;
    const int oy = sp / OW;
    const int ox = sp - oy * OW;
    const float* inb = in + (((size_t)bI * IH + oy * STRIDE) * IW + ox * STRIDE) * 64;

    float c[2][4][4];
#pragma unroll
    for (int m = 0; m < 2; m++)
#pragma unroll
        for (int n = 0; n < 4; n++)
#pragma unroll
            for (int e = 0; e < 4; e++) c[m][n][e] = 0.f;

    __syncthreads();

    // fill chunk ch into stage s: BN+ReLU, bf16 hi/lo split, pack k-pairs
    auto fill = [&](int s, int ch) {
        const int w = ch >> 1;
        const int ic0 = (ch & 1) * 32;
        const int ky = w / 3, kx = w - ky * 3;
        uint32_t* aH = smu + s * STG;
        uint32_t* aL = aH + 2176;
        const float* src = inb + (ky * IW + kx) * 64 + ic0 + khalf * 16;
        float xs[16];
#pragma unroll
        for (int j = 0; j < 4; j++) {
            float4 v = *(const float4*)(src + j * 4);
            int icb = ic0 + khalf * 16 + j * 4;
            float4 sc = *(const float4*)&sBn[icb];
            float4 sh = *(const float4*)&sBn[64 + icb];
            xs[j * 4 + 0] = fmaxf(fmaf(v.x, sc.x, sh.x), 0.f);
            xs[j * 4 + 1] = fmaxf(fmaf(v.y, sc.y, sh.y), 0.f);
            xs[j * 4 + 2] = fmaxf(fmaf(v.z, sc.z, sh.z), 0.f);
            xs[j * 4 + 3] = fmaxf(fmaf(v.w, sc.w, sh.w), 0.f);
        }
#pragma unroll
        for (int jj = 0; jj < 8; jj++) {
            float r0, r1;
            uint16_t h0 = f2bf(xs[2 * jj], r0);
            uint16_t h1 = f2bf(xs[2 * jj + 1], r1);
            uint16_t l0 = f2bf(r0, r0);
            uint16_t l1 = f2bf(r1, r1);
            int k2g = khalf * 8 + jj;
            aH[k2g * 136 + row] = ((uint32_t)h1 << 16) | h0;
            aL[k2g * 136 + row] = ((uint32_t)l1 << 16) | l0;
        }
    };

    fill(0, 0);
    __syncthreads();

#pragma unroll 1
    for (int ch = 0; ch < 18; ch++) {
        if (ch + 1 < 18) fill((ch + 1) & 1, ch + 1);

        const uint32_t* aH = smu + (ch & 1) * STG;
        const uint32_t* aL = aH + 2176;
        const uint4* wp = Wf + (size_t)(ch * 2 + wn) * 256 + lane;
#pragma unroll
        for (int step = 0; step < 2; step++) {
            uint32_t ah[2][4], al[2][4];
#pragma unroll
            for (int m = 0; m < 2; m++) {
                int rf = wm * 32 + m * 16 + lg;
                int k2 = step * 8 + lt;
                ah[m][0] = aH[k2 * 136 + rf];
                ah[m][1] = aH[k2 * 136 + rf + 8];
                ah[m][2] = aH[(k2 + 4) * 136 + rf];
                ah[m][3] = aH[(k2 + 4) * 136 + rf + 8];
                al[m][0] = aL[k2 * 136 + rf];
                al[m][1] = aL[k2 * 136 + rf + 8];
                al[m][2] = aL[(k2 + 4) * 136 + rf];
                al[m][3] = aL[(k2 + 4) * 136 + rf + 8];
            }
#pragma unroll
            for (int nf = 0; nf < 4; nf++) {
                uint4 b = wp[nf * 64 + step * 32];
#pragma unroll
                for (int m = 0; m < 2; m++) {
                    mma_bf16(c[m][nf], ah[m], b.x, b.y);   // hi*hi
                    mma_bf16(c[m][nf], ah[m], b.z, b.w);   // hi*lo
                    mma_bf16(c[m][nf], al[m], b.x, b.y);   // lo*hi
                }
            }
        }
        __syncthreads();
    }

    // fused stats: per-col partials, stride-4 shuffle reduce, smem, atomics
#pragma unroll
    for (int nf = 0; nf < 4; nf++) {
#pragma unroll
        for (int e = 0; e < 2; e++) {      // e=0 -> col0 (c[.][0],c[.][2]); e=1 -> col1
            float s = c[0][nf][e] + c[0][nf][e + 2] + c[1][nf][e] + c[1][nf][e + 2];
            float q = c[0][nf][e] * c[0][nf][e] + c[0][nf][e + 2] * c[0][nf][e + 2] +
                      c[1][nf][e] * c[1][nf][e] + c[1][nf][e + 2] * c[1][nf][e + 2];
#pragma unroll
            for (int o = 16; o >= 4; o >>= 1) {
                s += __shfl_down_sync(0xffffffffu, s, o);
                q += __shfl_down_sync(0xffffffffu, q, o);
            }
            if (lane < 4) {
                int col = wn * 32 + nf * 8 + lane * 2 + e;
                sred[0][col][warp] = s;
                sred[1][col][warp] = q;
            }
        }
    }

    // output stores
#pragma unroll
    for (int m = 0; m < 2; m++) {
        int r = blockIdx.x * 128 + wm * 32 + m * 16 + lg;
#pragma unroll
        for (int nf = 0; nf < 4; nf++) {
            int col = wn * 32 + nf * 8 + lt * 2;
            *(float2*)(out + (size_t)r * 64 + col) =
                make_float2(c[m][nf][0], c[m][nf][1]);
            *(float2*)(out + (size_t)(r + 8) * 64 + col) =
                make_float2(c[m][nf][2], c[m][nf][3]);
        }
    }
    __syncthreads();
    if (tid < 128) {
        int si = tid >> 6, col = tid & 63;
        int wbase = (col < 32) ? 0 : 4;     // cols 0..31 in warps 0..3 (wn=0)
        float v = sred[si][col][wbase] + sred[si][col][wbase + 1] +
                  sred[si][col][wbase + 2] + sred[si][col][wbase + 3];
        atomicAdd(&slot[si * 64 + col], v);
    }
}

// ---- relation network: one block per batch element ------------------------
__global__ void __launch_bounds__(256) relation_kernel(
    const float* __restrict__ conv4, const float* __restrict__ lat,
    const float* __restrict__ Wg1, const float* __restrict__ bg1,
    const float* __restrict__ Wg2, const float* __restrict__ bg2,
    const float* __restrict__ Wg3, const float* __restrict__ bg3,
    const float* __restrict__ stats, const float* __restrict__ bn_g,
    const float* __restrict__ bn_b, float invN,
    int im, float* __restrict__ gout) {
    extern __shared__ float sm[];
    float* sW2 = sm;
    float* sW3 = sm + 4096;
    float* sTi = sm + 8192;
    float* sTj = sm + 9792;
    float* sCT = sm + 11392;
    float* sTw = sm + 13042;
    float* sH  = sm + 13108;
    float* sGp = sm + 15156;
    __shared__ float sBn[128];

    const int tid = threadIdx.x;
    const int b = blockIdx.x;
    const int lane = tid & 31, warp = tid >> 5;

    if (tid < 64) {
        float s = stats[tid], q = stats[64 + tid];
        float mean = s * invN;
        float var = q * invN - mean * mean;
        float sc = bn_g[tid] * rsqrtf(var + 1e-5f);
        sBn[tid] = sc;
        sBn[64 + tid] = bn_b[tid] - mean * sc;
    }
    for (int i = tid; i < 4096; i += 256) {
        sW2[i] = Wg2[i];
        sW3[i] = Wg3[i];
    }
    __syncthreads();

    const float invS = 1.f / (d_Ssum[im] + 1e-9f);
    const float* aRow = lat + ((size_t)b * 4 + 2 + im) * 64;
    const float* wRow = lat + ((size_t)b * 4 + im) * 64;

    for (int i = tid; i < 1600; i += 256) {
        int p = i >> 6, cc = i & 63;
        float v = conv4[((size_t)b * 25 + p) * 64 + cc];
        v = fmaxf(fmaf(v, sBn[cc], sBn[64 + cc]), 0.f);
        v *= expf(aRow[cc]) * invS;
        sCT[p * 66 + cc] = v;
    }
    if (tid < 50) {
        int p = tid % 25, cc = tid / 25;
        sCT[p * 66 + 64 + cc] = (cc == 0) ? (float)(p % 5) - 2.f : (float)(p / 5) - 2.f;
    }
    if (tid < 64) {
        float acc = bg1[tid];
        for (int cc = 0; cc < 64; cc++)
            acc = fmaf(wRow[cc], Wg1[(132 + cc) * 64 + tid], acc);
        sTw[tid] = acc;
    }
    __syncthreads();

    for (int o = tid; o < 1600; o += 256) {
        int p = o >> 6, h = o & 63;
        float aj = 0.f, ai = 0.f;
        for (int cc = 0; cc < 66; cc++) {
            float ctv = sCT[p * 66 + cc];
            aj = fmaf(ctv, Wg1[cc * 64 + h], aj);
            ai = fmaf(ctv, Wg1[(66 + cc) * 64 + h], ai);
        }
        sTj[p * 64 + h] = aj;
        sTi[p * 64 + h] = ai;
    }
    __syncthreads();

    const float twA = sTw[lane], twB = sTw[lane + 32];
    const float b2A = bg2[lane], b2B = bg2[lane + 32];
    const float b3A = bg3[lane], b3B = bg3[lane + 32];
    float gA = 0.f, gB = 0.f;
    float* hw = sH + warp * 256;

    for (int it = 0; it < 20; it++) {
        const int base = it * 32 + warp * 4;
#pragma unroll
        for (int s = 0; s < 4; s++) {
            int pr = base + s;
            bool vld = pr < 625;
            int p = vld ? pr / 25 : 0, qq = vld ? pr % 25 : 0;
            hw[lane * 4 + s] = fmaxf(sTi[p * 64 + lane] + sTj[qq * 64 + lane] + twA, 0.f);
            hw[(lane + 32) * 4 + s] =
                fmaxf(sTi[p * 64 + lane + 32] + sTj[qq * 64 + lane + 32] + twB, 0.f);
        }
        __syncwarp();

        float a0[4], a1[4];
#pragma unroll
        for (int s = 0; s < 4; s++) { a0[s] = b2A; a1[s] = b2B; }
#pragma unroll 8
        for (int k = 0; k < 64; k++) {
            float w0 = sW2[k * 64 + lane], w1 = sW2[k * 64 + lane + 32];
            float4 hv = *(float4*)&hw[k * 4];
            a0[0] = fmaf(hv.x, w0, a0[0]); a1[0] = fmaf(hv.x, w1, a1[0]);
            a0[1] = fmaf(hv.y, w0, a0[1]); a1[1] = fmaf(hv.y, w1, a1[1]);
            a0[2] = fmaf(hv.z, w0, a0[2]); a1[2] = fmaf(hv.z, w1, a1[2]);
            a0[3] = fmaf(hv.w, w0, a0[3]); a1[3] = fmaf(hv.w, w1, a1[3]);
        }
        __syncwarp();
#pragma unroll
        for (int s = 0; s < 4; s++) {
            hw[lane * 4 + s] = fmaxf(a0[s], 0.f);
            hw[(lane + 32) * 4 + s] = fmaxf(a1[s], 0.f);
        }
        __syncwarp();

#pragma unroll
        for (int s = 0; s < 4; s++) { a0[s] = b3A; a1[s] = b3B; }
#pragma unroll 8
        for (int k = 0; k < 64; k++) {
            float w0 = sW3[k * 64 + lane], w1 = sW3[k * 64 + lane + 32];
            float4 hv = *(float4*)&hw[k * 4];
            a0[0] = fmaf(hv.x, w0, a0[0]); a1[0] = fmaf(hv.x, w1, a1[0]);
            a0[1] = fmaf(hv.y, w0, a0[1]); a1[1] = fmaf(hv.y, w1, a1[1]);
            a0[2] = fmaf(hv.z, w0, a0[2]); a1[2] = fmaf(hv.z, w1, a1[2]);
            a0[3] = fmaf(hv.w, w0, a0[3]); a1[3] = fmaf(hv.w, w1, a1[3]);
        }
#pragma unroll
        for (int s = 0; s < 4; s++) {
            if (base + s < 625) {
                gA += fmaxf(a0[s], 0.f);
                gB += fmaxf(a1[s], 0.f);
            }
        }
        __syncwarp();
    }
    sGp[warp * 64 + lane] = gA;
    sGp[warp * 64 + lane + 32] = gB;
    __syncthreads();
    if (tid < 64) {
        float s = 0.f;
#pragma unroll
        for (int w = 0; w < 8; w++) s += sGp[w * 64 + tid];
        gout[(size_t)b * 64 + tid] = s;
    }
}

__global__ void final_head_kernel(const float* __restrict__ lat,
                                  const float* __restrict__ Wf1, const float* __restrict__ bf1,
                                  const float* __restrict__ Wf2, const float* __restrict__ bf2,
                                  const float* __restrict__ Wf3, const float* __restrict__ bf3,
                                  float* __restrict__ out) {
    __shared__ float sh1[8][64];
    int tid = threadIdx.x, lane = tid & 31, warp = tid >> 5;
    int b = blockIdx.x * 8 + warp;
    float a0 = bf1[lane], a1 = bf1[lane + 32];
    const float* g0 = d_g0 + (size_t)b * 64;
    const float* g1 = d_g1 + (size_t)b * 64;
    const float* lr = lat + (size_t)b * 256;
    for (int k = 0; k < 64; k++) {
        float g = g0[k];
        a0 = fmaf(g, Wf1[k * 64 + lane], a0);
        a1 = fmaf(g, Wf1[k * 64 + lane + 32], a1);
    }
    for (int k = 0; k < 64; k++) {
        float g = g1[k];
        a0 = fmaf(g, Wf1[(64 + k) * 64 + lane], a0);
        a1 = fmaf(g, Wf1[(64 + k) * 64 + lane + 32], a1);
    }
    for (int k = 0; k < 256; k++) {
        float g = lr[k];
        a0 = fmaf(g, Wf1[(128 + k) * 64 + lane], a0);
        a1 = fmaf(g, Wf1[(128 + k) * 64 + lane + 32], a1);
    }
    sh1[warp][lane] = fmaxf(a0, 0.f);
    sh1[warp][lane + 32] = fmaxf(a1, 0.f);
    __syncwarp();
    float c = bf2[lane];
    for (int k = 0; k < 64; k++) c = fmaf(sh1[warp][k], Wf2[k * 32 + lane], c);
    c = fmaxf(c, 0.f);
    float v = c * Wf3[lane];
#pragma unroll
    for (int o = 16; o; o >>= 1) v += __shfl_down_sync(0xffffffffu, v, o);
    if (lane == 0) out[b] = v + bf3[0];
}

extern "C" void kernel_launch(void* const* d_in, const int* in_sizes, int n_in,
                              void* d_out, int out_size) {
    const float* x0 = (const float*)d_in[0];
    const float* x1 = (const float*)d_in[1];
    const float* lat = (const float*)d_in[2];
    const float* Wc1 = (const float*)d_in[3];
    const float* Wc2 = (const float*)d_in[4];
    const float* Wc3 = (const float*)d_in[5];
    const float* Wc4 = (const float*)d_in[6];
    const float* bng = (const float*)d_in[7];
    const float* bnb = (const float*)d_in[8];
    const float* Wg1 = (const float*)d_in[9];
    const float* bg1 = (const float*)d_in[10];
    const float* Wg2 = (const float*)d_in[11];
    const float* bg2 = (const float*)d_in[12];
    const float* Wg3 = (const float*)d_in[13];
    const float* bg3 = (const float*)d_in[14];
    const float* Wf1 = (const float*)d_in[15];
    const float* bf1 = (const float*)d_in[16];
    const float* Wf2 = (const float*)d_in[17];
    const float* bf2 = (const float*)d_in[18];
    const float* Wf3 = (const float*)d_in[19];
    const float* bf3 = (const float*)d_in[20];
    float* out = (float*)d_out;

    float *buf1, *buf2, *buf3, *buf4, *wt1, *statsA, *g0p, *g1p;
    uint4 *wf2, *wf3, *wf4;
    cudaGetSymbolAddress((void**)&buf1, d_buf1);
    cudaGetSymbolAddress((void**)&buf2, d_buf2);
    cudaGetSymbolAddress((void**)&buf3, d_buf3);
    cudaGetSymbolAddress((void**)&buf4, d_buf4);
    cudaGetSymbolAddress((void**)&wt1, d_Wt1);
    cudaGetSymbolAddress((void**)&wf2, d_Wf2);
    cudaGetSymbolAddress((void**)&wf3, d_Wf3);
    cudaGetSymbolAddress((void**)&wf4, d_Wf4);
    cudaGetSymbolAddress((void**)&statsA, d_statsA);
    cudaGetSymbolAddress((void**)&g0p, d_g0);
    cudaGetSymbolAddress((void**)&g1p, d_g1);

    const int REL_SMEM = 15668 * 4;
    cudaFuncSetAttribute(relation_kernel, cudaFuncAttributeMaxDynamicSharedMemorySize, REL_SMEM);
    const int MMA_SMEM = 2 * 4352 * 4;   // 34816 B
    cudaFuncSetAttribute(conv_mma3_kernel<25, 25, 23, 23, 1>,
                         cudaFuncAttributeMaxDynamicSharedMemorySize, MMA_SMEM);
    cudaFuncSetAttribute(conv_mma3_kernel<23, 23, 11, 11, 2>,
                         cudaFuncAttributeMaxDynamicSharedMemorySize, MMA_SMEM);
    cudaFuncSetAttribute(conv_mma3_kernel<11, 11, 5, 5, 2>,
                         cudaFuncAttributeMaxDynamicSharedMemorySize, MMA_SMEM);

    zero_misc_kernel<<<1, 1024>>>();
    prep_weights_kernel<<<36, 256>>>(Wc1, Wc2, Wc3, Wc4);
    att_sum_kernel<<<64, 512>>>(lat);

    for (int im = 0; im < 2; im++) {
        const float* x = im ? x1 : x0;
        float* gp = im ? g1p : g0p;
        float* sl = statsA + im * 4 * 128;

        conv1_kernel<<<10000, 256>>>(x, wt1, buf1, sl + 0 * 128);
        conv_mma3_kernel<25, 25, 23, 23, 1><<<4232, 256, MMA_SMEM>>>(
            buf1, wf2, buf2, sl + 0 * 128, bng + 0, bnb + 0, 1.f / 640000.f,
            sl + 1 * 128);
        conv_mma3_kernel<23, 23, 11, 11, 2><<<968, 256, MMA_SMEM>>>(
            buf2, wf3, buf3, sl + 1 * 128, bng + 64, bnb + 64, 1.f / 541696.f,
            sl + 2 * 128);
        conv_mma3_kernel<11, 11, 5, 5, 2><<<200, 256, MMA_SMEM>>>(
            buf3, wf4, buf4, sl + 2 * 128, bng + 128, bnb + 128, 1.f / 123904.f,
            sl + 3 * 128);
        relation_kernel<<<1024, 256, REL_SMEM>>>(
            buf4, lat, Wg1, bg1, Wg2, bg2, Wg3, bg3,
            sl + 3 * 128, bng + 192, bnb + 192, 1.f / 25600.f, im, gp);
    }
    final_head_kernel<<<128, 256>>>(lat, Wf1, bf1, Wf2, bf2, Wf3, bf3, out);
}